// round 1
// baseline (speedup 1.0000x reference)
#include <cuda_runtime.h>
#include <math.h>

#define NN 50000
#define EE 600000
#define DDIM 128
#define HH 8

// ---------------- scratch (static device memory; no allocs) ----------------
static __device__ float    g_h[NN * DDIM];          // LN1 output
static __device__ float    g_qkv[NN * 3 * DDIM];    // [N][3][H][16]: q(scaled),k,v
static __device__ float    g_a[EE * HH];            // raw attention logits
static __device__ float    g_ex[EE * HH];           // exp(a - max)
static __device__ unsigned g_mx[NN * HH];           // segment max (monotone-uint)
static __device__ float    g_den[NN * HH];          // segment sum of ex
static __device__ float    g_agg[NN * DDIM];        // aggregated messages
static __device__ float    g_x[NN * DDIM];          // residual stream
static __device__ float    g_y[NN * DDIM];          // LN2 output
static __device__ float    g_t[NN * 4 * DDIM];      // MLP hidden

static __device__ __forceinline__ unsigned f2mono(float x) {
    unsigned u = __float_as_uint(x);
    return (u & 0x80000000u) ? ~u : (u | 0x80000000u);
}
static __device__ __forceinline__ float mono2f(unsigned u) {
    return __uint_as_float((u & 0x80000000u) ? (u & 0x7FFFFFFFu) : ~u);
}

// ---------------- init: zero accumulators ----------------
__global__ void init_kernel() {
    int i = blockIdx.x * blockDim.x + threadIdx.x;
    int stride = gridDim.x * blockDim.x;
    for (int j = i; j < NN * DDIM / 4; j += stride)
        ((float4*)g_agg)[j] = make_float4(0.f, 0.f, 0.f, 0.f);
    for (int j = i; j < NN * HH; j += stride) {
        g_mx[j]  = 0u;     // == f2mono(-inf) lower bound
        g_den[j] = 0.f;
    }
}

// ---------------- LayerNorm: one warp per row of 128 ----------------
__global__ void ln_kernel(const float* __restrict__ in,
                          const float* __restrict__ g,
                          const float* __restrict__ b,
                          float* __restrict__ out, int n) {
    int wid  = (blockIdx.x * blockDim.x + threadIdx.x) >> 5;
    int lane = threadIdx.x & 31;
    if (wid >= n) return;
    const float4* row = (const float4*)(in + (size_t)wid * DDIM);
    float4 x = row[lane];
    float s  = x.x + x.y + x.z + x.w;
    float s2 = x.x * x.x + x.y * x.y + x.z * x.z + x.w * x.w;
    #pragma unroll
    for (int o = 16; o > 0; o >>= 1) {
        s  += __shfl_xor_sync(0xFFFFFFFFu, s,  o);
        s2 += __shfl_xor_sync(0xFFFFFFFFu, s2, o);
    }
    float mu  = s  * (1.0f / 128.0f);
    float var = s2 * (1.0f / 128.0f) - mu * mu;
    float r   = rsqrtf(var + 1e-5f);
    float4 gg = ((const float4*)g)[lane];
    float4 bb = ((const float4*)b)[lane];
    float4 o4;
    o4.x = (x.x - mu) * r * gg.x + bb.x;
    o4.y = (x.y - mu) * r * gg.y + bb.y;
    o4.z = (x.z - mu) * r * gg.z + bb.z;
    o4.w = (x.w - mu) * r * gg.w + bb.w;
    ((float4*)(out + (size_t)wid * DDIM))[lane] = o4;
}

// ---------------- GEMM: C[n,M] = epi(A[n,K] @ W[K,M] + bias) ----------------
// block: 256 threads, 64 rows x 128-col tile; warp ty -> rows ty*8..+7 (uniform
// LDS broadcast of A), lane tx -> 4 cols via LDS.128 of W. 8x4 acc per thread.
// EPI: 0 = scale first 128 cols by D^-0.5 (qkv)
//      1 = add residual res[row*M+col]
//      2 = tanh-gelu
static __device__ __forceinline__ float gelu_f(float v) {
    float t = tanhf(0.7978845608028654f * (v + 0.044715f * v * v * v));
    return 0.5f * v * (1.0f + t);
}

template <int EPI>
__global__ __launch_bounds__(256)
void gemm_kernel(const float* __restrict__ A,
                 const float* __restrict__ W,
                 const float* __restrict__ bias,
                 const float* __restrict__ res,
                 float* __restrict__ C,
                 int n, int M, int K) {
    extern __shared__ float sm[];
    float* Ws = sm;                 // 128*128 floats (64 KB)
    float* As = sm + 128 * 128;     // 64*128 floats  (32 KB)
    const int tid = threadIdx.x;
    const int ty = tid >> 5, tx = tid & 31;
    const int row0 = blockIdx.x * 64;
    const int MT = M >> 7, KT = K >> 7;

    for (int ct = 0; ct < MT; ct++) {
        float acc[8][4];
        #pragma unroll
        for (int i = 0; i < 8; i++)
            #pragma unroll
            for (int c = 0; c < 4; c++) acc[i][c] = 0.f;

        for (int kt = 0; kt < KT; kt++) {
            // stage A tile: 64 x 128
            #pragma unroll
            for (int j = 0; j < 8; j++) {
                int f = tid + j * 256;
                int r = f >> 5, c4 = f & 31;
                float4 v = make_float4(0.f, 0.f, 0.f, 0.f);
                if (row0 + r < n)
                    v = *(const float4*)(A + (size_t)(row0 + r) * K + kt * 128 + c4 * 4);
                *(float4*)(As + r * 128 + c4 * 4) = v;
            }
            // stage W tile: 128 x 128
            #pragma unroll
            for (int j = 0; j < 16; j++) {
                int f = tid + j * 256;
                int r = f >> 5, c4 = f & 31;
                *(float4*)(Ws + r * 128 + c4 * 4) =
                    *(const float4*)(W + (size_t)(kt * 128 + r) * M + ct * 128 + c4 * 4);
            }
            __syncthreads();
            #pragma unroll 16
            for (int k = 0; k < 128; k++) {
                float4 w = *(const float4*)(Ws + k * 128 + tx * 4);
                #pragma unroll
                for (int i = 0; i < 8; i++) {
                    float a = As[(ty * 8 + i) * 128 + k];
                    acc[i][0] += a * w.x;
                    acc[i][1] += a * w.y;
                    acc[i][2] += a * w.z;
                    acc[i][3] += a * w.w;
                }
            }
            __syncthreads();
        }

        const int col = ct * 128 + tx * 4;
        float4 bb = *(const float4*)(bias + col);
        #pragma unroll
        for (int i = 0; i < 8; i++) {
            int r = row0 + ty * 8 + i;
            if (r >= n) continue;
            float4 v;
            v.x = acc[i][0] + bb.x;
            v.y = acc[i][1] + bb.y;
            v.z = acc[i][2] + bb.z;
            v.w = acc[i][3] + bb.w;
            if (EPI == 0) {
                if (col < 128) {  // q columns -> scale by D^-0.5
                    const float sc = 0.08838834764831845f;
                    v.x *= sc; v.y *= sc; v.z *= sc; v.w *= sc;
                }
            } else if (EPI == 1) {
                float4 rr = *(const float4*)(res + (size_t)r * M + col);
                v.x += rr.x; v.y += rr.y; v.z += rr.z; v.w += rr.w;
            } else if (EPI == 2) {
                v.x = gelu_f(v.x); v.y = gelu_f(v.y);
                v.z = gelu_f(v.z); v.w = gelu_f(v.w);
            }
            *(float4*)(C + (size_t)r * M + col) = v;
        }
    }
}

// ---------------- edge scores + segment max ----------------
__global__ void scores_kernel(const int* __restrict__ src,
                              const int* __restrict__ dst,
                              const float* __restrict__ dist,
                              const float* __restrict__ path) {
    int t = blockIdx.x * blockDim.x + threadIdx.x;
    if (t >= EE * HH) return;
    int e = t >> 3, h = t & 7;
    int s = src[e], d = dst[e];
    const float4* qp = (const float4*)(g_qkv + (size_t)s * 384 + h * 16);
    const float4* kp = (const float4*)(g_qkv + (size_t)d * 384 + 128 + h * 16);
    float dot = 0.f;
    #pragma unroll
    for (int j = 0; j < 4; j++) {
        float4 q = qp[j], k = kp[j];
        dot += q.x * k.x + q.y * k.y + q.z * k.z + q.w * k.w;
    }
    float a = dot + dist[t] + path[t];
    g_a[t] = a;
    atomicMax(&g_mx[d * HH + h], f2mono(a));
}

// ---------------- exp + segment denominator ----------------
__global__ void exden_kernel(const int* __restrict__ dst) {
    int t = blockIdx.x * blockDim.x + threadIdx.x;
    if (t >= EE * HH) return;
    int e = t >> 3, h = t & 7;
    int d = dst[e];
    float m = mono2f(g_mx[d * HH + h]);
    float ex = expf(g_a[t] - m);
    g_ex[t] = ex;
    atomicAdd(&g_den[d * HH + h], ex);
}

// ---------------- weighted scatter-aggregate: 32 lanes per edge ----------------
__global__ void agg_kernel(const int* __restrict__ src,
                           const int* __restrict__ dst) {
    int g = blockIdx.x * blockDim.x + threadIdx.x;
    int e = g >> 5;
    if (e >= EE) return;
    int lane = g & 31;
    int s = src[e], d = dst[e];
    int h = lane >> 2;  // 4 lanes per head (16 dims each)
    float sa = g_ex[e * HH + h] / g_den[d * HH + h];
    float4 v = *(const float4*)(g_qkv + (size_t)s * 384 + 256 + lane * 4);
    float* out = g_agg + (size_t)d * DDIM + lane * 4;
    atomicAdd(out + 0, v.x * sa);
    atomicAdd(out + 1, v.y * sa);
    atomicAdd(out + 2, v.z * sa);
    atomicAdd(out + 3, v.w * sa);
}

// ---------------- launch ----------------
extern "C" void kernel_launch(void* const* d_in, const int* in_sizes, int n_in,
                              void* d_out, int out_size) {
    const float* node_feature = (const float*)d_in[0];
    const float* dist_attn    = (const float*)d_in[1];
    const float* path_attn    = (const float*)d_in[2];
    const int*   src          = (const int*)d_in[3];
    const int*   dst          = (const int*)d_in[4];
    const float* ln1_g        = (const float*)d_in[5];
    const float* ln1_b        = (const float*)d_in[6];
    const float* qkv_w        = (const float*)d_in[7];
    const float* qkv_b        = (const float*)d_in[8];
    const float* in_proj_w    = (const float*)d_in[9];
    const float* in_proj_b    = (const float*)d_in[10];
    const float* res_ln_g     = (const float*)d_in[11];
    const float* res_ln_b     = (const float*)d_in[12];
    const float* mlp_w1       = (const float*)d_in[13];
    const float* mlp_b1       = (const float*)d_in[14];
    const float* mlp_w2       = (const float*)d_in[15];
    const float* mlp_b2       = (const float*)d_in[16];
    float* out = (float*)d_out;

    const size_t SMEM = (size_t)(128 * 128 + 64 * 128) * sizeof(float);  // 96 KB
    cudaFuncSetAttribute(gemm_kernel<0>, cudaFuncAttributeMaxDynamicSharedMemorySize, (int)SMEM);
    cudaFuncSetAttribute(gemm_kernel<1>, cudaFuncAttributeMaxDynamicSharedMemorySize, (int)SMEM);
    cudaFuncSetAttribute(gemm_kernel<2>, cudaFuncAttributeMaxDynamicSharedMemorySize, (int)SMEM);

    void* p;
    cudaGetSymbolAddress(&p, g_h);    float* ph   = (float*)p;
    cudaGetSymbolAddress(&p, g_qkv);  float* pqkv = (float*)p;
    cudaGetSymbolAddress(&p, g_agg);  float* pagg = (float*)p;
    cudaGetSymbolAddress(&p, g_x);    float* px   = (float*)p;
    cudaGetSymbolAddress(&p, g_y);    float* py   = (float*)p;
    cudaGetSymbolAddress(&p, g_t);    float* pt   = (float*)p;

    const int GEMM_BLOCKS = (NN + 63) / 64;  // 782
    const int LN_BLOCKS   = (NN + 7) / 8;    // warp per row, 8 warps/block
    const int EH_BLOCKS   = (EE * HH + 255) / 256;
    const int AGG_BLOCKS  = (EE * 32) / 256;

    init_kernel<<<2048, 256>>>();
    ln_kernel<<<LN_BLOCKS, 256>>>(node_feature, ln1_g, ln1_b, ph, NN);
    gemm_kernel<0><<<GEMM_BLOCKS, 256, SMEM>>>(ph, qkv_w, qkv_b, nullptr, pqkv, NN, 384, 128);
    scores_kernel<<<EH_BLOCKS, 256>>>(src, dst, dist_attn, path_attn);
    exden_kernel<<<EH_BLOCKS, 256>>>(dst);
    agg_kernel<<<AGG_BLOCKS, 256>>>(src, dst);
    gemm_kernel<1><<<GEMM_BLOCKS, 256, SMEM>>>(pagg, in_proj_w, in_proj_b, ph, px, NN, 128, 128);
    ln_kernel<<<LN_BLOCKS, 256>>>(px, res_ln_g, res_ln_b, py, NN);
    gemm_kernel<2><<<GEMM_BLOCKS, 256, SMEM>>>(py, mlp_w1, mlp_b1, nullptr, pt, NN, 512, 128);
    gemm_kernel<1><<<GEMM_BLOCKS, 256, SMEM>>>(pt, mlp_w2, mlp_b2, px, out, NN, 128, 512);
}

// round 6
// speedup vs baseline: 2.0942x; 2.0942x over previous
#include <cuda_runtime.h>
#include <math.h>

#define NN 50000
#define EE 600000
#define DDIM 128
#define HH 8

// ---------------- scratch (static device memory; no allocs) ----------------
static __device__ float    g_h[NN * DDIM];          // LN1 output
static __device__ float    g_qkv[NN * 3 * DDIM];    // [N][3][H][16]: q(scaled),k,v
static __device__ float    g_a[EE * HH];            // raw attention logits
static __device__ unsigned g_mx[NN * HH];           // segment max (monotone-uint)
static __device__ float    g_den[NN * HH];          // seg sum of ex -> reciprocal
static __device__ float    g_agg[NN * DDIM];        // UNNORMALIZED aggregated msgs
static __device__ float    g_x[NN * DDIM];          // residual stream
static __device__ float    g_y[NN * DDIM];          // LN2 output

static __device__ __forceinline__ unsigned f2mono(float x) {
    unsigned u = __float_as_uint(x);
    return (u & 0x80000000u) ? ~u : (u | 0x80000000u);
}
static __device__ __forceinline__ float mono2f(unsigned u) {
    return __uint_as_float((u & 0x80000000u) ? (u & 0x7FFFFFFFu) : ~u);
}

// ---------------- init: zero accumulators ----------------
__global__ void init_kernel() {
    int i = blockIdx.x * blockDim.x + threadIdx.x;
    int stride = gridDim.x * blockDim.x;
    for (int j = i; j < NN * DDIM / 4; j += stride)
        ((float4*)g_agg)[j] = make_float4(0.f, 0.f, 0.f, 0.f);
    for (int j = i; j < NN * HH; j += stride) {
        g_mx[j]  = 0u;     // == f2mono(-inf) lower bound
        g_den[j] = 0.f;
    }
}

// ---------------- LayerNorm: one warp per row of 128 ----------------
__global__ void ln_kernel(const float* __restrict__ in,
                          const float* __restrict__ g,
                          const float* __restrict__ b,
                          float* __restrict__ out, int n) {
    int wid  = (blockIdx.x * blockDim.x + threadIdx.x) >> 5;
    int lane = threadIdx.x & 31;
    if (wid >= n) return;
    const float4* row = (const float4*)(in + (size_t)wid * DDIM);
    float4 x = row[lane];
    float s  = x.x + x.y + x.z + x.w;
    float s2 = x.x * x.x + x.y * x.y + x.z * x.z + x.w * x.w;
    #pragma unroll
    for (int o = 16; o > 0; o >>= 1) {
        s  += __shfl_xor_sync(0xFFFFFFFFu, s,  o);
        s2 += __shfl_xor_sync(0xFFFFFFFFu, s2, o);
    }
    float mu  = s  * (1.0f / 128.0f);
    float var = s2 * (1.0f / 128.0f) - mu * mu;
    float r   = rsqrtf(var + 1e-5f);
    float4 gg = ((const float4*)g)[lane];
    float4 bb = ((const float4*)b)[lane];
    float4 o4;
    o4.x = (x.x - mu) * r * gg.x + bb.x;
    o4.y = (x.y - mu) * r * gg.y + bb.y;
    o4.z = (x.z - mu) * r * gg.z + bb.z;
    o4.w = (x.w - mu) * r * gg.w + bb.w;
    ((float4*)(out + (size_t)wid * DDIM))[lane] = o4;
}

// ---------------- TF32 tensor-core GEMM ----------------
// C[n,M] = epi(preA(A)[n,K] @ W[K,M] + bias)
// PRE=1: multiply A row r, col c float4 by g_den[r*8 + c/16] (softmax rcp).
#define AS_STRIDE 36
#define BS_STRIDE 136
#define AS_BUF (128 * AS_STRIDE)
#define BS_BUF (32 * BS_STRIDE)

static __device__ __forceinline__ unsigned tf32r(float x) {
    unsigned u;
    asm("cvt.rna.tf32.f32 %0, %1;" : "=r"(u) : "f"(x));
    return u;
}

#define MMA_TF32(d, a, b0, b1)                                              \
    asm volatile("mma.sync.aligned.m16n8k8.row.col.f32.tf32.tf32.f32 "      \
                 "{%0,%1,%2,%3}, {%4,%5,%6,%7}, {%8,%9}, {%0,%1,%2,%3};"    \
                 : "+f"(d[0]), "+f"(d[1]), "+f"(d[2]), "+f"(d[3])           \
                 : "r"(a[0]), "r"(a[1]), "r"(a[2]), "r"(a[3]),              \
                   "r"(b0), "r"(b1))

static __device__ __forceinline__ float gelu_f(float v) {
    float t = tanhf(0.7978845608028654f * (v + 0.044715f * v * v * v));
    return 0.5f * v * (1.0f + t);
}

template <int EPI, int PRE>
__global__ __launch_bounds__(256)
void gemm_tc(const float* __restrict__ A,
             const float* __restrict__ W,
             const float* __restrict__ bias,
             const float* __restrict__ res,
             float* __restrict__ C,
             int n, int M, int K) {
    extern __shared__ unsigned sm[];
    unsigned* As = sm;                  // 2 x 128 x 36
    unsigned* Bs = sm + 2 * AS_BUF;     // 2 x 32 x 136

    const int tid  = threadIdx.x;
    const int lane = tid & 31, warp = tid >> 5;
    const int lg = lane >> 2, lr = lane & 3;
    const int wm = warp & 3,  wn = warp >> 2;
    const int row0 = blockIdx.y * 128;
    const int col0 = blockIdx.x * 128;
    const int KT = K >> 5;

    float acc[2][8][4];
    #pragma unroll
    for (int mt = 0; mt < 2; mt++)
        #pragma unroll
        for (int nt = 0; nt < 8; nt++)
            #pragma unroll
            for (int i = 0; i < 4; i++) acc[mt][nt][i] = 0.f;

    float4 ra[4], rb[4];

    // -------- prologue: load + store tile 0 --------
    #pragma unroll
    for (int j = 0; j < 4; j++) {
        int f = tid + j * 256;
        int r = f >> 3, kc = f & 7;
        float4 v = make_float4(0.f, 0.f, 0.f, 0.f);
        if (row0 + r < n) {
            v = *(const float4*)(A + (size_t)(row0 + r) * K + kc * 4);
            if (PRE) {
                float iv = g_den[(row0 + r) * 8 + ((kc * 4) >> 4)];
                v.x *= iv; v.y *= iv; v.z *= iv; v.w *= iv;
            }
        }
        ra[j] = v;
        int k = f >> 5, nc = f & 31;
        rb[j] = *(const float4*)(W + (size_t)k * M + col0 + nc * 4);
    }
    #pragma unroll
    for (int j = 0; j < 4; j++) {
        int f = tid + j * 256;
        int r = f >> 3, kc = f & 7;
        uint4 t;
        t.x = tf32r(ra[j].x); t.y = tf32r(ra[j].y);
        t.z = tf32r(ra[j].z); t.w = tf32r(ra[j].w);
        *(uint4*)(As + r * AS_STRIDE + kc * 4) = t;
        int k = f >> 5, nc = f & 31;
        uint4 u;
        u.x = tf32r(rb[j].x); u.y = tf32r(rb[j].y);
        u.z = tf32r(rb[j].z); u.w = tf32r(rb[j].w);
        *(uint4*)(Bs + k * BS_STRIDE + nc * 4) = u;
    }
    __syncthreads();

    for (int kt = 0; kt < KT; kt++) {
        const int cur = kt & 1;
        if (kt + 1 < KT) {
            #pragma unroll
            for (int j = 0; j < 4; j++) {
                int f = tid + j * 256;
                int r = f >> 3, kc = f & 7;
                float4 v = make_float4(0.f, 0.f, 0.f, 0.f);
                if (row0 + r < n) {
                    v = *(const float4*)(A + (size_t)(row0 + r) * K + (kt + 1) * 32 + kc * 4);
                    if (PRE) {
                        float iv = g_den[(row0 + r) * 8 + (((kt + 1) * 32 + kc * 4) >> 4)];
                        v.x *= iv; v.y *= iv; v.z *= iv; v.w *= iv;
                    }
                }
                ra[j] = v;
                int k = f >> 5, nc = f & 31;
                rb[j] = *(const float4*)(W + (size_t)((kt + 1) * 32 + k) * M + col0 + nc * 4);
            }
        }
        const unsigned* Ab = As + cur * AS_BUF;
        const unsigned* Bb = Bs + cur * BS_BUF;
        #pragma unroll
        for (int ks = 0; ks < 4; ks++) {
            unsigned a[2][4];
            #pragma unroll
            for (int mt = 0; mt < 2; mt++) {
                const unsigned* ap = Ab + (wm * 32 + mt * 16 + lg) * AS_STRIDE + ks * 8 + lr;
                a[mt][0] = ap[0];
                a[mt][1] = ap[8 * AS_STRIDE];
                a[mt][2] = ap[4];
                a[mt][3] = ap[8 * AS_STRIDE + 4];
            }
            #pragma unroll
            for (int nt = 0; nt < 8; nt++) {
                const unsigned* bp = Bb + (ks * 8 + lr) * BS_STRIDE + wn * 64 + nt * 8 + lg;
                unsigned b0 = bp[0];
                unsigned b1 = bp[4 * BS_STRIDE];
                MMA_TF32(acc[0][nt], a[0], b0, b1);
                MMA_TF32(acc[1][nt], a[1], b0, b1);
            }
        }
        if (kt + 1 < KT) {
            unsigned* Ad = As + (cur ^ 1) * AS_BUF;
            unsigned* Bd = Bs + (cur ^ 1) * BS_BUF;
            #pragma unroll
            for (int j = 0; j < 4; j++) {
                int f = tid + j * 256;
                int r = f >> 3, kc = f & 7;
                uint4 t;
                t.x = tf32r(ra[j].x); t.y = tf32r(ra[j].y);
                t.z = tf32r(ra[j].z); t.w = tf32r(ra[j].w);
                *(uint4*)(Ad + r * AS_STRIDE + kc * 4) = t;
                int k = f >> 5, nc = f & 31;
                uint4 u;
                u.x = tf32r(rb[j].x); u.y = tf32r(rb[j].y);
                u.z = tf32r(rb[j].z); u.w = tf32r(rb[j].w);
                *(uint4*)(Bd + k * BS_STRIDE + nc * 4) = u;
            }
        }
        __syncthreads();
    }

    const float sc = 0.08838834764831845f;  // D^-0.5
    #pragma unroll
    for (int mt = 0; mt < 2; mt++) {
        #pragma unroll
        for (int nt = 0; nt < 8; nt++) {
            int r = row0 + wm * 32 + mt * 16 + lg;
            int c = col0 + wn * 64 + nt * 8 + lr * 2;
            float b0 = bias[c], b1 = bias[c + 1];
            float v0 = acc[mt][nt][0] + b0;
            float v1 = acc[mt][nt][1] + b1;
            float v2 = acc[mt][nt][2] + b0;
            float v3 = acc[mt][nt][3] + b1;
            if (EPI == 0) {
                if (blockIdx.x == 0) {
                    v0 *= sc; v1 *= sc; v2 *= sc; v3 *= sc;
                }
            } else if (EPI == 2) {
                v0 = gelu_f(v0); v1 = gelu_f(v1);
                v2 = gelu_f(v2); v3 = gelu_f(v3);
            }
            if (r < n) {
                float2 o = make_float2(v0, v1);
                if (EPI == 1) {
                    float2 rr = *(const float2*)(res + (size_t)r * M + c);
                    o.x += rr.x; o.y += rr.y;
                }
                *(float2*)(C + (size_t)r * M + c) = o;
            }
            if (r + 8 < n) {
                float2 o = make_float2(v2, v3);
                if (EPI == 1) {
                    float2 rr = *(const float2*)(res + (size_t)(r + 8) * M + c);
                    o.x += rr.x; o.y += rr.y;
                }
                *(float2*)(C + (size_t)(r + 8) * M + c) = o;
            }
        }
    }
}

// ---------------- fused MLP: out = res + gelu(Y@W1+b1)@W2 + b2 ----------------
// Per 128-row block. Y staged once (tf32). 4 hidden chunks of 128:
// phase1 H_c = gelu(Y@W1[:,c]+b1) -> smem; phase2 acc2 += H_c @ W2[c,:].
#define YS_STRIDE 132
#define HS_STRIDE 132
#define FM_SMEM ((128 * YS_STRIDE + 128 * HS_STRIDE + 2 * BS_BUF) * 4)

__global__ __launch_bounds__(256)
void fmlp_kernel(const float* __restrict__ Y,
                 const float* __restrict__ W1,
                 const float* __restrict__ b1,
                 const float* __restrict__ W2,
                 const float* __restrict__ b2,
                 const float* __restrict__ res,
                 float* __restrict__ C, int n) {
    extern __shared__ unsigned sm[];
    unsigned* Ys = sm;                        // 128 x 132
    unsigned* Hs = sm + 128 * YS_STRIDE;      // 128 x 132
    unsigned* Bs = Hs + 128 * HS_STRIDE;      // 2 x 32 x 136

    const int tid  = threadIdx.x;
    const int lane = tid & 31, warp = tid >> 5;
    const int lg = lane >> 2, lr = lane & 3;
    const int wm = warp & 3,  wn = warp >> 2;
    const int row0 = blockIdx.x * 128;

    // stage Y tile (128 x 128) as tf32
    #pragma unroll
    for (int j = 0; j < 16; j++) {
        int f = tid + j * 256;
        int r = f >> 5, c4 = f & 31;
        float4 v = make_float4(0.f, 0.f, 0.f, 0.f);
        if (row0 + r < n)
            v = *(const float4*)(Y + (size_t)(row0 + r) * DDIM + c4 * 4);
        uint4 t;
        t.x = tf32r(v.x); t.y = tf32r(v.y);
        t.z = tf32r(v.z); t.w = tf32r(v.w);
        *(uint4*)(Ys + r * YS_STRIDE + c4 * 4) = t;
    }

    float acc2[2][8][4];
    #pragma unroll
    for (int mt = 0; mt < 2; mt++)
        #pragma unroll
        for (int nt = 0; nt < 8; nt++)
            #pragma unroll
            for (int i = 0; i < 4; i++) acc2[mt][nt][i] = 0.f;

    float4 rb[4];
    __syncthreads();

    for (int cch = 0; cch < 4; cch++) {
        // ---- phase 1: H = Y @ W1[:, cch*128 .. +128] ----
        float acc[2][8][4];
        #pragma unroll
        for (int mt = 0; mt < 2; mt++)
            #pragma unroll
            for (int nt = 0; nt < 8; nt++)
                #pragma unroll
                for (int i = 0; i < 4; i++) acc[mt][nt][i] = 0.f;

        // stage W1 k-step 0
        #pragma unroll
        for (int j = 0; j < 4; j++) {
            int f = tid + j * 256;
            int k = f >> 5, nc = f & 31;
            float4 v = *(const float4*)(W1 + (size_t)k * 512 + cch * 128 + nc * 4);
            uint4 u;
            u.x = tf32r(v.x); u.y = tf32r(v.y);
            u.z = tf32r(v.z); u.w = tf32r(v.w);
            *(uint4*)(Bs + k * BS_STRIDE + nc * 4) = u;
        }
        __syncthreads();

        #pragma unroll
        for (int kt = 0; kt < 4; kt++) {
            const int cur = kt & 1;
            if (kt < 3) {
                #pragma unroll
                for (int j = 0; j < 4; j++) {
                    int f = tid + j * 256;
                    int k = f >> 5, nc = f & 31;
                    rb[j] = *(const float4*)(W1 + (size_t)((kt + 1) * 32 + k) * 512 + cch * 128 + nc * 4);
                }
            }
            const unsigned* Bb = Bs + cur * BS_BUF;
            #pragma unroll
            for (int ks = 0; ks < 4; ks++) {
                unsigned a[2][4];
                #pragma unroll
                for (int mt = 0; mt < 2; mt++) {
                    const unsigned* ap = Ys + (wm * 32 + mt * 16 + lg) * YS_STRIDE + kt * 32 + ks * 8 + lr;
                    a[mt][0] = ap[0];
                    a[mt][1] = ap[8 * YS_STRIDE];
                    a[mt][2] = ap[4];
                    a[mt][3] = ap[8 * YS_STRIDE + 4];
                }
                #pragma unroll
                for (int nt = 0; nt < 8; nt++) {
                    const unsigned* bp = Bb + (ks * 8 + lr) * BS_STRIDE + wn * 64 + nt * 8 + lg;
                    unsigned b0 = bp[0];
                    unsigned b1v = bp[4 * BS_STRIDE];
                    MMA_TF32(acc[0][nt], a[0], b0, b1v);
                    MMA_TF32(acc[1][nt], a[1], b0, b1v);
                }
            }
            if (kt < 3) {
                unsigned* Bd = Bs + (cur ^ 1) * BS_BUF;
                #pragma unroll
                for (int j = 0; j < 4; j++) {
                    int f = tid + j * 256;
                    int k = f >> 5, nc = f & 31;
                    uint4 u;
                    u.x = tf32r(rb[j].x); u.y = tf32r(rb[j].y);
                    u.z = tf32r(rb[j].z); u.w = tf32r(rb[j].w);
                    *(uint4*)(Bd + k * BS_STRIDE + nc * 4) = u;
                }
            }
            __syncthreads();
        }

        // gelu + b1 -> Hs (tf32)
        #pragma unroll
        for (int mt = 0; mt < 2; mt++) {
            #pragma unroll
            for (int nt = 0; nt < 8; nt++) {
                int rloc = wm * 32 + mt * 16 + lg;
                int cloc = wn * 64 + nt * 8 + lr * 2;
                float bb0 = b1[cch * 128 + cloc];
                float bb1 = b1[cch * 128 + cloc + 1];
                uint2 p0, p1;
                p0.x = tf32r(gelu_f(acc[mt][nt][0] + bb0));
                p0.y = tf32r(gelu_f(acc[mt][nt][1] + bb1));
                p1.x = tf32r(gelu_f(acc[mt][nt][2] + bb0));
                p1.y = tf32r(gelu_f(acc[mt][nt][3] + bb1));
                *(uint2*)(Hs + rloc * HS_STRIDE + cloc) = p0;
                *(uint2*)(Hs + (rloc + 8) * HS_STRIDE + cloc) = p1;
            }
        }
        __syncthreads();

        // ---- phase 2: acc2 += H @ W2[cch*128 .. +128, :] ----
        #pragma unroll
        for (int j = 0; j < 4; j++) {
            int f = tid + j * 256;
            int k = f >> 5, nc = f & 31;
            float4 v = *(const float4*)(W2 + (size_t)(cch * 128 + k) * DDIM + nc * 4);
            uint4 u;
            u.x = tf32r(v.x); u.y = tf32r(v.y);
            u.z = tf32r(v.z); u.w = tf32r(v.w);
            *(uint4*)(Bs + k * BS_STRIDE + nc * 4) = u;
        }
        __syncthreads();

        #pragma unroll
        for (int kt = 0; kt < 4; kt++) {
            const int cur = kt & 1;
            if (kt < 3) {
                #pragma unroll
                for (int j = 0; j < 4; j++) {
                    int f = tid + j * 256;
                    int k = f >> 5, nc = f & 31;
                    rb[j] = *(const float4*)(W2 + (size_t)(cch * 128 + (kt + 1) * 32 + k) * DDIM + nc * 4);
                }
            }
            const unsigned* Bb = Bs + cur * BS_BUF;
            #pragma unroll
            for (int ks = 0; ks < 4; ks++) {
                unsigned a[2][4];
                #pragma unroll
                for (int mt = 0; mt < 2; mt++) {
                    const unsigned* ap = Hs + (wm * 32 + mt * 16 + lg) * HS_STRIDE + kt * 32 + ks * 8 + lr;
                    a[mt][0] = ap[0];
                    a[mt][1] = ap[8 * HS_STRIDE];
                    a[mt][2] = ap[4];
                    a[mt][3] = ap[8 * HS_STRIDE + 4];
                }
                #pragma unroll
                for (int nt = 0; nt < 8; nt++) {
                    const unsigned* bp = Bb + (ks * 8 + lr) * BS_STRIDE + wn * 64 + nt * 8 + lg;
                    unsigned b0 = bp[0];
                    unsigned b1v = bp[4 * BS_STRIDE];
                    MMA_TF32(acc2[0][nt], a[0], b0, b1v);
                    MMA_TF32(acc2[1][nt], a[1], b0, b1v);
                }
            }
            if (kt < 3) {
                unsigned* Bd = Bs + (cur ^ 1) * BS_BUF;
                #pragma unroll
                for (int j = 0; j < 4; j++) {
                    int f = tid + j * 256;
                    int k = f >> 5, nc = f & 31;
                    uint4 u;
                    u.x = tf32r(rb[j].x); u.y = tf32r(rb[j].y);
                    u.z = tf32r(rb[j].z); u.w = tf32r(rb[j].w);
                    *(uint4*)(Bd + k * BS_STRIDE + nc * 4) = u;
                }
            }
            __syncthreads();
        }
    }

    // epilogue: + b2 + res
    #pragma unroll
    for (int mt = 0; mt < 2; mt++) {
        #pragma unroll
        for (int nt = 0; nt < 8; nt++) {
            int r = row0 + wm * 32 + mt * 16 + lg;
            int c = wn * 64 + nt * 8 + lr * 2;
            float bb0 = b2[c], bb1 = b2[c + 1];
            if (r < n) {
                float2 rr = *(const float2*)(res + (size_t)r * DDIM + c);
                float2 o = make_float2(acc2[mt][nt][0] + bb0 + rr.x,
                                       acc2[mt][nt][1] + bb1 + rr.y);
                *(float2*)(C + (size_t)r * DDIM + c) = o;
            }
            if (r + 8 < n) {
                float2 rr = *(const float2*)(res + (size_t)(r + 8) * DDIM + c);
                float2 o = make_float2(acc2[mt][nt][2] + bb0 + rr.x,
                                       acc2[mt][nt][3] + bb1 + rr.y);
                *(float2*)(C + (size_t)(r + 8) * DDIM + c) = o;
            }
        }
    }
}

// ---------------- edge scores + segment max ----------------
__global__ void scores_kernel(const int* __restrict__ src,
                              const int* __restrict__ dst,
                              const float* __restrict__ dist,
                              const float* __restrict__ path) {
    int t = blockIdx.x * blockDim.x + threadIdx.x;
    if (t >= EE * HH) return;
    int e = t >> 3, h = t & 7;
    int s = src[e], d = dst[e];
    const float4* qp = (const float4*)(g_qkv + (size_t)s * 384 + h * 16);
    const float4* kp = (const float4*)(g_qkv + (size_t)d * 384 + 128 + h * 16);
    float dot = 0.f;
    #pragma unroll
    for (int j = 0; j < 4; j++) {
        float4 q = qp[j], k = kp[j];
        dot += q.x * k.x + q.y * k.y + q.z * k.z + q.w * k.w;
    }
    float a = dot + dist[t] + path[t];
    g_a[t] = a;
    atomicMax(&g_mx[d * HH + h], f2mono(a));
}

// ---------------- fused exp + denominator + unnormalized aggregate ----------------
__global__ void agg_kernel(const int* __restrict__ src,
                           const int* __restrict__ dst) {
    int g = blockIdx.x * blockDim.x + threadIdx.x;
    int e = g >> 5;
    if (e >= EE) return;
    int lane = g & 31;
    int s = src[e], d = dst[e];
    int h = lane >> 2;  // 4 lanes per head (16 dims each)
    float a  = g_a[e * HH + h];
    float m  = mono2f(g_mx[d * HH + h]);
    float ex = expf(a - m);
    if ((lane & 3) == 0)
        atomicAdd(&g_den[d * HH + h], ex);
    float4 v = *(const float4*)(g_qkv + (size_t)s * 384 + 256 + lane * 4);
    float4* out = (float4*)(g_agg + (size_t)d * DDIM + lane * 4);
    atomicAdd(out, make_float4(v.x * ex, v.y * ex, v.z * ex, v.w * ex));
}

// ---------------- reciprocal of denominators (0 for empty segments) ----------------
__global__ void rcp_kernel() {
    int i = blockIdx.x * blockDim.x + threadIdx.x;
    if (i >= NN * HH) return;
    float d = g_den[i];
    g_den[i] = (d > 0.f) ? (1.0f / d) : 0.f;
}

// ---------------- launch ----------------
extern "C" void kernel_launch(void* const* d_in, const int* in_sizes, int n_in,
                              void* d_out, int out_size) {
    const float* node_feature = (const float*)d_in[0];
    const float* dist_attn    = (const float*)d_in[1];
    const float* path_attn    = (const float*)d_in[2];
    const int*   src          = (const int*)d_in[3];
    const int*   dst          = (const int*)d_in[4];
    const float* ln1_g        = (const float*)d_in[5];
    const float* ln1_b        = (const float*)d_in[6];
    const float* qkv_w        = (const float*)d_in[7];
    const float* qkv_b        = (const float*)d_in[8];
    const float* in_proj_w    = (const float*)d_in[9];
    const float* in_proj_b    = (const float*)d_in[10];
    const float* res_ln_g     = (const float*)d_in[11];
    const float* res_ln_b     = (const float*)d_in[12];
    const float* mlp_w1       = (const float*)d_in[13];
    const float* mlp_b1       = (const float*)d_in[14];
    const float* mlp_w2       = (const float*)d_in[15];
    const float* mlp_b2       = (const float*)d_in[16];
    float* out = (float*)d_out;

    const int SMEM = (2 * AS_BUF + 2 * BS_BUF) * 4;  // 71680 B
    cudaFuncSetAttribute(gemm_tc<0, 0>, cudaFuncAttributeMaxDynamicSharedMemorySize, SMEM);
    cudaFuncSetAttribute(gemm_tc<1, 1>, cudaFuncAttributeMaxDynamicSharedMemorySize, SMEM);
    cudaFuncSetAttribute(fmlp_kernel, cudaFuncAttributeMaxDynamicSharedMemorySize, FM_SMEM);

    void* p;
    cudaGetSymbolAddress(&p, g_h);    float* ph   = (float*)p;
    cudaGetSymbolAddress(&p, g_qkv);  float* pqkv = (float*)p;
    cudaGetSymbolAddress(&p, g_agg);  float* pagg = (float*)p;
    cudaGetSymbolAddress(&p, g_x);    float* px   = (float*)p;
    cudaGetSymbolAddress(&p, g_y);    float* py   = (float*)p;

    const int RB = (NN + 127) / 128;         // 391 row blocks
    const int LN_BLOCKS = (NN + 7) / 8;
    const int EH_BLOCKS = (EE * HH + 255) / 256;
    const int AGG_BLOCKS = (EE * 32) / 256;

    init_kernel<<<2048, 256>>>();
    ln_kernel<<<LN_BLOCKS, 256>>>(node_feature, ln1_g, ln1_b, ph, NN);
    gemm_tc<0, 0><<<dim3(3, RB), 256, SMEM>>>(ph, qkv_w, qkv_b, nullptr, pqkv, NN, 384, 128);
    scores_kernel<<<EH_BLOCKS, 256>>>(src, dst, dist_attn, path_attn);
    agg_kernel<<<AGG_BLOCKS, 256>>>(src, dst);
    rcp_kernel<<<(NN * HH + 255) / 256, 256>>>();
    gemm_tc<1, 1><<<dim3(1, RB), 256, SMEM>>>(pagg, in_proj_w, in_proj_b, ph, px, NN, 128, 128);
    ln_kernel<<<LN_BLOCKS, 256>>>(px, res_ln_g, res_ln_b, py, NN);
    fmlp_kernel<<<RB, 256, FM_SMEM>>>(py, mlp_w1, mlp_b1, mlp_w2, mlp_b2, px, out, NN);
}

// round 7
// speedup vs baseline: 2.3240x; 1.1097x over previous
#include <cuda_runtime.h>
#include <math.h>

#define NN 50000
#define EE 600000
#define DDIM 128
#define HH 8
#define NB 196   // ceil(NN/256) scan blocks

// ---------------- scratch (static device memory; no allocs) ----------------
static __device__ float g_h[NN * DDIM];          // LN1 output
static __device__ float g_qkv[NN * 3 * DDIM];    // [N][3][H][16]: q(scaled),k,v
static __device__ float g_agg[NN * DDIM];        // NORMALIZED aggregated msgs
static __device__ float g_x[NN * DDIM];          // residual stream
static __device__ float g_y[NN * DDIM];          // LN2 output
static __device__ int   g_deg[NN];               // per-dst degree
static __device__ int   g_off[NN + 1];           // CSR offsets
static __device__ int   g_pos[NN];               // scatter cursors
static __device__ int   g_eid[EE];               // edge ids grouped by dst
static __device__ int   g_bsum[NB];              // scan block partials

// ---------------- CSR build ----------------
__global__ void zero_deg_kernel() {
    int i = blockIdx.x * blockDim.x + threadIdx.x;
    if (i < NN) g_deg[i] = 0;
}
__global__ void hist_kernel(const int* __restrict__ dst) {
    int e = blockIdx.x * blockDim.x + threadIdx.x;
    if (e < EE) atomicAdd(&g_deg[dst[e]], 1);
}
// block-local exclusive scan of g_deg -> g_off, block totals -> g_bsum
__global__ void scanA_kernel() {
    __shared__ int sh[256];
    int t = threadIdx.x;
    int i = blockIdx.x * 256 + t;
    int val = (i < NN) ? g_deg[i] : 0;
    sh[t] = val;
    #pragma unroll
    for (int o = 1; o < 256; o <<= 1) {
        __syncthreads();
        int x = (t >= o) ? sh[t - o] : 0;
        __syncthreads();
        sh[t] += x;
    }
    __syncthreads();
    int excl = sh[t] - val;
    if (i < NN) g_off[i] = excl;
    if (t == 255) g_bsum[blockIdx.x] = sh[255];
}
__global__ void scanB_kernel() {
    __shared__ int sh[256];
    int t = threadIdx.x;
    int val = (t < NB) ? g_bsum[t] : 0;
    sh[t] = val;
    #pragma unroll
    for (int o = 1; o < 256; o <<= 1) {
        __syncthreads();
        int x = (t >= o) ? sh[t - o] : 0;
        __syncthreads();
        sh[t] += x;
    }
    __syncthreads();
    if (t < NB) g_bsum[t] = sh[t] - val;
}
__global__ void scanC_kernel() {
    int i = blockIdx.x * 256 + threadIdx.x;
    if (i < NN) {
        int v = g_off[i] + g_bsum[blockIdx.x];
        g_off[i] = v;
        g_pos[i] = v;
    }
    if (i == 0) g_off[NN] = EE;
}
__global__ void scatter_kernel(const int* __restrict__ dst) {
    int e = blockIdx.x * blockDim.x + threadIdx.x;
    if (e >= EE) return;
    int d = dst[e];
    int p = atomicAdd(&g_pos[d], 1);
    g_eid[p] = e;
}

// ---------------- fused attention: one warp per destination node ----------------
// Online softmax over the dst's edge list; k[d] register-resident; all segment
// state (max, den, weighted-V) in registers. Writes normalized g_agg directly.
__global__ void attn_kernel(const int* __restrict__ src,
                            const float* __restrict__ dist,
                            const float* __restrict__ path) {
    int w = (blockIdx.x * blockDim.x + threadIdx.x) >> 5;
    if (w >= NN) return;
    int lane = threadIdx.x & 31;
    int h = lane >> 2;  // 4 lanes per head, 16 dims/head
    int beg = g_off[w], end = g_off[w + 1];
    float4 kv = *(const float4*)(g_qkv + (size_t)w * 384 + 128 + lane * 4);
    float4 acc = make_float4(0.f, 0.f, 0.f, 0.f);
    float m = -1e30f, den = 0.f;

    if (beg < end) {
        int e = g_eid[beg];
        int s = src[e];
        float4 qv = *(const float4*)(g_qkv + (size_t)s * 384 + lane * 4);
        float4 vv = *(const float4*)(g_qkv + (size_t)s * 384 + 256 + lane * 4);
        float dp = dist[e * 8 + h] + path[e * 8 + h];
        for (int idx = beg; idx < end; idx++) {
            // prefetch next edge while computing current
            float4 qv1, vv1; float dp1 = 0.f;
            bool more = (idx + 1 < end);
            if (more) {
                int e1 = g_eid[idx + 1];
                int s1 = src[e1];
                qv1 = *(const float4*)(g_qkv + (size_t)s1 * 384 + lane * 4);
                vv1 = *(const float4*)(g_qkv + (size_t)s1 * 384 + 256 + lane * 4);
                dp1 = dist[e1 * 8 + h] + path[e1 * 8 + h];
            }
            float dot = qv.x * kv.x + qv.y * kv.y + qv.z * kv.z + qv.w * kv.w;
            dot += __shfl_xor_sync(0xFFFFFFFFu, dot, 1);
            dot += __shfl_xor_sync(0xFFFFFFFFu, dot, 2);
            float a = dot + dp;
            float mn = fmaxf(m, a);
            float corr = expf(m - mn);
            float p = expf(a - mn);
            den = den * corr + p;
            acc.x = acc.x * corr + vv.x * p;
            acc.y = acc.y * corr + vv.y * p;
            acc.z = acc.z * corr + vv.z * p;
            acc.w = acc.w * corr + vv.w * p;
            m = mn;
            if (more) { qv = qv1; vv = vv1; dp = dp1; }
        }
    }
    float inv = (den > 0.f) ? (1.0f / den) : 0.f;
    acc.x *= inv; acc.y *= inv; acc.z *= inv; acc.w *= inv;
    *(float4*)(g_agg + (size_t)w * DDIM + lane * 4) = acc;
}

// ---------------- LayerNorm: one warp per row of 128 ----------------
__global__ void ln_kernel(const float* __restrict__ in,
                          const float* __restrict__ g,
                          const float* __restrict__ b,
                          float* __restrict__ out, int n) {
    int wid  = (blockIdx.x * blockDim.x + threadIdx.x) >> 5;
    int lane = threadIdx.x & 31;
    if (wid >= n) return;
    const float4* row = (const float4*)(in + (size_t)wid * DDIM);
    float4 x = row[lane];
    float s  = x.x + x.y + x.z + x.w;
    float s2 = x.x * x.x + x.y * x.y + x.z * x.z + x.w * x.w;
    #pragma unroll
    for (int o = 16; o > 0; o >>= 1) {
        s  += __shfl_xor_sync(0xFFFFFFFFu, s,  o);
        s2 += __shfl_xor_sync(0xFFFFFFFFu, s2, o);
    }
    float mu  = s  * (1.0f / 128.0f);
    float var = s2 * (1.0f / 128.0f) - mu * mu;
    float r   = rsqrtf(var + 1e-5f);
    float4 gg = ((const float4*)g)[lane];
    float4 bb = ((const float4*)b)[lane];
    float4 o4;
    o4.x = (x.x - mu) * r * gg.x + bb.x;
    o4.y = (x.y - mu) * r * gg.y + bb.y;
    o4.z = (x.z - mu) * r * gg.z + bb.z;
    o4.w = (x.w - mu) * r * gg.w + bb.w;
    ((float4*)(out + (size_t)wid * DDIM))[lane] = o4;
}

// ---------------- TF32 tensor-core GEMM ----------------
#define AS_STRIDE 36
#define BS_STRIDE 136
#define AS_BUF (128 * AS_STRIDE)
#define BS_BUF (32 * BS_STRIDE)

static __device__ __forceinline__ unsigned tf32r(float x) {
    unsigned u;
    asm("cvt.rna.tf32.f32 %0, %1;" : "=r"(u) : "f"(x));
    return u;
}

#define MMA_TF32(d, a, b0, b1)                                              \
    asm volatile("mma.sync.aligned.m16n8k8.row.col.f32.tf32.tf32.f32 "      \
                 "{%0,%1,%2,%3}, {%4,%5,%6,%7}, {%8,%9}, {%0,%1,%2,%3};"    \
                 : "+f"(d[0]), "+f"(d[1]), "+f"(d[2]), "+f"(d[3])           \
                 : "r"(a[0]), "r"(a[1]), "r"(a[2]), "r"(a[3]),              \
                   "r"(b0), "r"(b1))

static __device__ __forceinline__ float gelu_f(float v) {
    float t = tanhf(0.7978845608028654f * (v + 0.044715f * v * v * v));
    return 0.5f * v * (1.0f + t);
}

template <int EPI>
__global__ __launch_bounds__(256)
void gemm_tc(const float* __restrict__ A,
             const float* __restrict__ W,
             const float* __restrict__ bias,
             const float* __restrict__ res,
             float* __restrict__ C,
             int n, int M, int K) {
    extern __shared__ unsigned sm[];
    unsigned* As = sm;                  // 2 x 128 x 36
    unsigned* Bs = sm + 2 * AS_BUF;     // 2 x 32 x 136

    const int tid  = threadIdx.x;
    const int lane = tid & 31, warp = tid >> 5;
    const int lg = lane >> 2, lr = lane & 3;
    const int wm = warp & 3,  wn = warp >> 2;
    const int row0 = blockIdx.y * 128;
    const int col0 = blockIdx.x * 128;
    const int KT = K >> 5;

    float acc[2][8][4];
    #pragma unroll
    for (int mt = 0; mt < 2; mt++)
        #pragma unroll
        for (int nt = 0; nt < 8; nt++)
            #pragma unroll
            for (int i = 0; i < 4; i++) acc[mt][nt][i] = 0.f;

    float4 ra[4], rb[4];

    #pragma unroll
    for (int j = 0; j < 4; j++) {
        int f = tid + j * 256;
        int r = f >> 3, kc = f & 7;
        float4 v = make_float4(0.f, 0.f, 0.f, 0.f);
        if (row0 + r < n)
            v = *(const float4*)(A + (size_t)(row0 + r) * K + kc * 4);
        ra[j] = v;
        int k = f >> 5, nc = f & 31;
        rb[j] = *(const float4*)(W + (size_t)k * M + col0 + nc * 4);
    }
    #pragma unroll
    for (int j = 0; j < 4; j++) {
        int f = tid + j * 256;
        int r = f >> 3, kc = f & 7;
        uint4 t;
        t.x = tf32r(ra[j].x); t.y = tf32r(ra[j].y);
        t.z = tf32r(ra[j].z); t.w = tf32r(ra[j].w);
        *(uint4*)(As + r * AS_STRIDE + kc * 4) = t;
        int k = f >> 5, nc = f & 31;
        uint4 u;
        u.x = tf32r(rb[j].x); u.y = tf32r(rb[j].y);
        u.z = tf32r(rb[j].z); u.w = tf32r(rb[j].w);
        *(uint4*)(Bs + k * BS_STRIDE + nc * 4) = u;
    }
    __syncthreads();

    for (int kt = 0; kt < KT; kt++) {
        const int cur = kt & 1;
        if (kt + 1 < KT) {
            #pragma unroll
            for (int j = 0; j < 4; j++) {
                int f = tid + j * 256;
                int r = f >> 3, kc = f & 7;
                float4 v = make_float4(0.f, 0.f, 0.f, 0.f);
                if (row0 + r < n)
                    v = *(const float4*)(A + (size_t)(row0 + r) * K + (kt + 1) * 32 + kc * 4);
                ra[j] = v;
                int k = f >> 5, nc = f & 31;
                rb[j] = *(const float4*)(W + (size_t)((kt + 1) * 32 + k) * M + col0 + nc * 4);
            }
        }
        const unsigned* Ab = As + cur * AS_BUF;
        const unsigned* Bb = Bs + cur * BS_BUF;
        #pragma unroll
        for (int ks = 0; ks < 4; ks++) {
            unsigned a[2][4];
            #pragma unroll
            for (int mt = 0; mt < 2; mt++) {
                const unsigned* ap = Ab + (wm * 32 + mt * 16 + lg) * AS_STRIDE + ks * 8 + lr;
                a[mt][0] = ap[0];
                a[mt][1] = ap[8 * AS_STRIDE];
                a[mt][2] = ap[4];
                a[mt][3] = ap[8 * AS_STRIDE + 4];
            }
            #pragma unroll
            for (int nt = 0; nt < 8; nt++) {
                const unsigned* bp = Bb + (ks * 8 + lr) * BS_STRIDE + wn * 64 + nt * 8 + lg;
                unsigned b0 = bp[0];
                unsigned b1 = bp[4 * BS_STRIDE];
                MMA_TF32(acc[0][nt], a[0], b0, b1);
                MMA_TF32(acc[1][nt], a[1], b0, b1);
            }
        }
        if (kt + 1 < KT) {
            unsigned* Ad = As + (cur ^ 1) * AS_BUF;
            unsigned* Bd = Bs + (cur ^ 1) * BS_BUF;
            #pragma unroll
            for (int j = 0; j < 4; j++) {
                int f = tid + j * 256;
                int r = f >> 3, kc = f & 7;
                uint4 t;
                t.x = tf32r(ra[j].x); t.y = tf32r(ra[j].y);
                t.z = tf32r(ra[j].z); t.w = tf32r(ra[j].w);
                *(uint4*)(Ad + r * AS_STRIDE + kc * 4) = t;
                int k = f >> 5, nc = f & 31;
                uint4 u;
                u.x = tf32r(rb[j].x); u.y = tf32r(rb[j].y);
                u.z = tf32r(rb[j].z); u.w = tf32r(rb[j].w);
                *(uint4*)(Bd + k * BS_STRIDE + nc * 4) = u;
            }
        }
        __syncthreads();
    }

    const float sc = 0.08838834764831845f;  // D^-0.5
    #pragma unroll
    for (int mt = 0; mt < 2; mt++) {
        #pragma unroll
        for (int nt = 0; nt < 8; nt++) {
            int r = row0 + wm * 32 + mt * 16 + lg;
            int c = col0 + wn * 64 + nt * 8 + lr * 2;
            float b0 = bias[c], b1 = bias[c + 1];
            float v0 = acc[mt][nt][0] + b0;
            float v1 = acc[mt][nt][1] + b1;
            float v2 = acc[mt][nt][2] + b0;
            float v3 = acc[mt][nt][3] + b1;
            if (EPI == 0) {
                if (blockIdx.x == 0) {
                    v0 *= sc; v1 *= sc; v2 *= sc; v3 *= sc;
                }
            }
            if (r < n) {
                float2 o = make_float2(v0, v1);
                if (EPI == 1) {
                    float2 rr = *(const float2*)(res + (size_t)r * M + c);
                    o.x += rr.x; o.y += rr.y;
                }
                *(float2*)(C + (size_t)r * M + c) = o;
            }
            if (r + 8 < n) {
                float2 o = make_float2(v2, v3);
                if (EPI == 1) {
                    float2 rr = *(const float2*)(res + (size_t)(r + 8) * M + c);
                    o.x += rr.x; o.y += rr.y;
                }
                *(float2*)(C + (size_t)(r + 8) * M + c) = o;
            }
        }
    }
}

// ---------------- fused MLP: out = res + gelu(Y@W1+b1)@W2 + b2 ----------------
#define YS_STRIDE 132
#define HS_STRIDE 132
#define FM_SMEM ((128 * YS_STRIDE + 128 * HS_STRIDE + 2 * BS_BUF) * 4)

__global__ __launch_bounds__(256)
void fmlp_kernel(const float* __restrict__ Y,
                 const float* __restrict__ W1,
                 const float* __restrict__ b1,
                 const float* __restrict__ W2,
                 const float* __restrict__ b2,
                 const float* __restrict__ res,
                 float* __restrict__ C, int n) {
    extern __shared__ unsigned sm[];
    unsigned* Ys = sm;                        // 128 x 132
    unsigned* Hs = sm + 128 * YS_STRIDE;      // 128 x 132
    unsigned* Bs = Hs + 128 * HS_STRIDE;      // 2 x 32 x 136

    const int tid  = threadIdx.x;
    const int lane = tid & 31, warp = tid >> 5;
    const int lg = lane >> 2, lr = lane & 3;
    const int wm = warp & 3,  wn = warp >> 2;
    const int row0 = blockIdx.x * 128;

    #pragma unroll
    for (int j = 0; j < 16; j++) {
        int f = tid + j * 256;
        int r = f >> 5, c4 = f & 31;
        float4 v = make_float4(0.f, 0.f, 0.f, 0.f);
        if (row0 + r < n)
            v = *(const float4*)(Y + (size_t)(row0 + r) * DDIM + c4 * 4);
        uint4 t;
        t.x = tf32r(v.x); t.y = tf32r(v.y);
        t.z = tf32r(v.z); t.w = tf32r(v.w);
        *(uint4*)(Ys + r * YS_STRIDE + c4 * 4) = t;
    }

    float acc2[2][8][4];
    #pragma unroll
    for (int mt = 0; mt < 2; mt++)
        #pragma unroll
        for (int nt = 0; nt < 8; nt++)
            #pragma unroll
            for (int i = 0; i < 4; i++) acc2[mt][nt][i] = 0.f;

    float4 rb[4];
    __syncthreads();

    for (int cch = 0; cch < 4; cch++) {
        float acc[2][8][4];
        #pragma unroll
        for (int mt = 0; mt < 2; mt++)
            #pragma unroll
            for (int nt = 0; nt < 8; nt++)
                #pragma unroll
                for (int i = 0; i < 4; i++) acc[mt][nt][i] = 0.f;

        #pragma unroll
        for (int j = 0; j < 4; j++) {
            int f = tid + j * 256;
            int k = f >> 5, nc = f & 31;
            float4 v = *(const float4*)(W1 + (size_t)k * 512 + cch * 128 + nc * 4);
            uint4 u;
            u.x = tf32r(v.x); u.y = tf32r(v.y);
            u.z = tf32r(v.z); u.w = tf32r(v.w);
            *(uint4*)(Bs + k * BS_STRIDE + nc * 4) = u;
        }
        __syncthreads();

        #pragma unroll
        for (int kt = 0; kt < 4; kt++) {
            const int cur = kt & 1;
            if (kt < 3) {
                #pragma unroll
                for (int j = 0; j < 4; j++) {
                    int f = tid + j * 256;
                    int k = f >> 5, nc = f & 31;
                    rb[j] = *(const float4*)(W1 + (size_t)((kt + 1) * 32 + k) * 512 + cch * 128 + nc * 4);
                }
            }
            const unsigned* Bb = Bs + cur * BS_BUF;
            #pragma unroll
            for (int ks = 0; ks < 4; ks++) {
                unsigned a[2][4];
                #pragma unroll
                for (int mt = 0; mt < 2; mt++) {
                    const unsigned* ap = Ys + (wm * 32 + mt * 16 + lg) * YS_STRIDE + kt * 32 + ks * 8 + lr;
                    a[mt][0] = ap[0];
                    a[mt][1] = ap[8 * YS_STRIDE];
                    a[mt][2] = ap[4];
                    a[mt][3] = ap[8 * YS_STRIDE + 4];
                }
                #pragma unroll
                for (int nt = 0; nt < 8; nt++) {
                    const unsigned* bp = Bb + (ks * 8 + lr) * BS_STRIDE + wn * 64 + nt * 8 + lg;
                    unsigned b0 = bp[0];
                    unsigned b1v = bp[4 * BS_STRIDE];
                    MMA_TF32(acc[0][nt], a[0], b0, b1v);
                    MMA_TF32(acc[1][nt], a[1], b0, b1v);
                }
            }
            if (kt < 3) {
                unsigned* Bd = Bs + (cur ^ 1) * BS_BUF;
                #pragma unroll
                for (int j = 0; j < 4; j++) {
                    int f = tid + j * 256;
                    int k = f >> 5, nc = f & 31;
                    uint4 u;
                    u.x = tf32r(rb[j].x); u.y = tf32r(rb[j].y);
                    u.z = tf32r(rb[j].z); u.w = tf32r(rb[j].w);
                    *(uint4*)(Bd + k * BS_STRIDE + nc * 4) = u;
                }
            }
            __syncthreads();
        }

        #pragma unroll
        for (int mt = 0; mt < 2; mt++) {
            #pragma unroll
            for (int nt = 0; nt < 8; nt++) {
                int rloc = wm * 32 + mt * 16 + lg;
                int cloc = wn * 64 + nt * 8 + lr * 2;
                float bb0 = b1[cch * 128 + cloc];
                float bb1 = b1[cch * 128 + cloc + 1];
                uint2 p0, p1;
                p0.x = tf32r(gelu_f(acc[mt][nt][0] + bb0));
                p0.y = tf32r(gelu_f(acc[mt][nt][1] + bb1));
                p1.x = tf32r(gelu_f(acc[mt][nt][2] + bb0));
                p1.y = tf32r(gelu_f(acc[mt][nt][3] + bb1));
                *(uint2*)(Hs + rloc * HS_STRIDE + cloc) = p0;
                *(uint2*)(Hs + (rloc + 8) * HS_STRIDE + cloc) = p1;
            }
        }
        __syncthreads();

        #pragma unroll
        for (int j = 0; j < 4; j++) {
            int f = tid + j * 256;
            int k = f >> 5, nc = f & 31;
            float4 v = *(const float4*)(W2 + (size_t)(cch * 128 + k) * DDIM + nc * 4);
            uint4 u;
            u.x = tf32r(v.x); u.y = tf32r(v.y);
            u.z = tf32r(v.z); u.w = tf32r(v.w);
            *(uint4*)(Bs + k * BS_STRIDE + nc * 4) = u;
        }
        __syncthreads();

        #pragma unroll
        for (int kt = 0; kt < 4; kt++) {
            const int cur = kt & 1;
            if (kt < 3) {
                #pragma unroll
                for (int j = 0; j < 4; j++) {
                    int f = tid + j * 256;
                    int k = f >> 5, nc = f & 31;
                    rb[j] = *(const float4*)(W2 + (size_t)(cch * 128 + (kt + 1) * 32 + k) * DDIM + nc * 4);
                }
            }
            const unsigned* Bb = Bs + cur * BS_BUF;
            #pragma unroll
            for (int ks = 0; ks < 4; ks++) {
                unsigned a[2][4];
                #pragma unroll
                for (int mt = 0; mt < 2; mt++) {
                    const unsigned* ap = Hs + (wm * 32 + mt * 16 + lg) * HS_STRIDE + kt * 32 + ks * 8 + lr;
                    a[mt][0] = ap[0];
                    a[mt][1] = ap[8 * HS_STRIDE];
                    a[mt][2] = ap[4];
                    a[mt][3] = ap[8 * HS_STRIDE + 4];
                }
                #pragma unroll
                for (int nt = 0; nt < 8; nt++) {
                    const unsigned* bp = Bb + (ks * 8 + lr) * BS_STRIDE + wn * 64 + nt * 8 + lg;
                    unsigned b0 = bp[0];
                    unsigned b1v = bp[4 * BS_STRIDE];
                    MMA_TF32(acc2[0][nt], a[0], b0, b1v);
                    MMA_TF32(acc2[1][nt], a[1], b0, b1v);
                }
            }
            if (kt < 3) {
                unsigned* Bd = Bs + (cur ^ 1) * BS_BUF;
                #pragma unroll
                for (int j = 0; j < 4; j++) {
                    int f = tid + j * 256;
                    int k = f >> 5, nc = f & 31;
                    uint4 u;
                    u.x = tf32r(rb[j].x); u.y = tf32r(rb[j].y);
                    u.z = tf32r(rb[j].z); u.w = tf32r(rb[j].w);
                    *(uint4*)(Bd + k * BS_STRIDE + nc * 4) = u;
                }
            }
            __syncthreads();
        }
    }

    #pragma unroll
    for (int mt = 0; mt < 2; mt++) {
        #pragma unroll
        for (int nt = 0; nt < 8; nt++) {
            int r = row0 + wm * 32 + mt * 16 + lg;
            int c = wn * 64 + nt * 8 + lr * 2;
            float bb0 = b2[c], bb1 = b2[c + 1];
            if (r < n) {
                float2 rr = *(const float2*)(res + (size_t)r * DDIM + c);
                float2 o = make_float2(acc2[mt][nt][0] + bb0 + rr.x,
                                       acc2[mt][nt][1] + bb1 + rr.y);
                *(float2*)(C + (size_t)r * DDIM + c) = o;
            }
            if (r + 8 < n) {
                float2 rr = *(const float2*)(res + (size_t)(r + 8) * DDIM + c);
                float2 o = make_float2(acc2[mt][nt][2] + bb0 + rr.x,
                                       acc2[mt][nt][3] + bb1 + rr.y);
                *(float2*)(C + (size_t)(r + 8) * DDIM + c) = o;
            }
        }
    }
}

// ---------------- launch ----------------
extern "C" void kernel_launch(void* const* d_in, const int* in_sizes, int n_in,
                              void* d_out, int out_size) {
    const float* node_feature = (const float*)d_in[0];
    const float* dist_attn    = (const float*)d_in[1];
    const float* path_attn    = (const float*)d_in[2];
    const int*   src          = (const int*)d_in[3];
    const int*   dst          = (const int*)d_in[4];
    const float* ln1_g        = (const float*)d_in[5];
    const float* ln1_b        = (const float*)d_in[6];
    const float* qkv_w        = (const float*)d_in[7];
    const float* qkv_b        = (const float*)d_in[8];
    const float* in_proj_w    = (const float*)d_in[9];
    const float* in_proj_b    = (const float*)d_in[10];
    const float* res_ln_g     = (const float*)d_in[11];
    const float* res_ln_b     = (const float*)d_in[12];
    const float* mlp_w1       = (const float*)d_in[13];
    const float* mlp_b1       = (const float*)d_in[14];
    const float* mlp_w2       = (const float*)d_in[15];
    const float* mlp_b2       = (const float*)d_in[16];
    float* out = (float*)d_out;

    const int SMEM = (2 * AS_BUF + 2 * BS_BUF) * 4;  // 71680 B
    cudaFuncSetAttribute(gemm_tc<0>, cudaFuncAttributeMaxDynamicSharedMemorySize, SMEM);
    cudaFuncSetAttribute(gemm_tc<1>, cudaFuncAttributeMaxDynamicSharedMemorySize, SMEM);
    cudaFuncSetAttribute(fmlp_kernel, cudaFuncAttributeMaxDynamicSharedMemorySize, FM_SMEM);

    void* p;
    cudaGetSymbolAddress(&p, g_h);    float* ph   = (float*)p;
    cudaGetSymbolAddress(&p, g_qkv);  float* pqkv = (float*)p;
    cudaGetSymbolAddress(&p, g_agg);  float* pagg = (float*)p;
    cudaGetSymbolAddress(&p, g_x);    float* px   = (float*)p;
    cudaGetSymbolAddress(&p, g_y);    float* py   = (float*)p;

    const int RB = (NN + 127) / 128;           // 391 row blocks
    const int LN_BLOCKS = (NN + 7) / 8;
    const int E_BLOCKS  = (EE + 255) / 256;
    const int N_BLOCKS  = (NN + 255) / 256;    // == NB
    const int ATTN_BLOCKS = (NN * 32 + 255) / 256;

    // CSR build
    zero_deg_kernel<<<N_BLOCKS, 256>>>();
    hist_kernel<<<E_BLOCKS, 256>>>(dst);
    scanA_kernel<<<NB, 256>>>();
    scanB_kernel<<<1, 256>>>();
    scanC_kernel<<<NB, 256>>>();
    scatter_kernel<<<E_BLOCKS, 256>>>(dst);

    // main pipeline
    ln_kernel<<<LN_BLOCKS, 256>>>(node_feature, ln1_g, ln1_b, ph, NN);
    gemm_tc<0><<<dim3(3, RB), 256, SMEM>>>(ph, qkv_w, qkv_b, nullptr, pqkv, NN, 384, 128);
    attn_kernel<<<ATTN_BLOCKS, 256>>>(src, dist_attn, path_attn);
    gemm_tc<1><<<dim3(1, RB), 256, SMEM>>>(pagg, in_proj_w, in_proj_b, ph, px, NN, 128, 128);
    ln_kernel<<<LN_BLOCKS, 256>>>(px, res_ln_g, res_ln_b, py, NN);
    fmlp_kernel<<<RB, 256, FM_SMEM>>>(py, mlp_w1, mlp_b1, mlp_w2, mlp_b2, px, out, NN);
}

// round 9
// speedup vs baseline: 2.8034x; 1.2063x over previous
#include <cuda_runtime.h>
#include <cuda_fp16.h>
#include <math.h>

#define NN 50000
#define EE 600000
#define DDIM 128
#define HH 8
#define NB 196   // ceil(NN/256) scan blocks

// ---------------- scratch (static device memory; no allocs) ----------------
static __device__ float g_h[NN * DDIM];          // LN1 output
static __device__ float g_qkv[NN * 3 * DDIM];    // [N][3][H][16]: q(scaled),k,v
static __device__ float g_agg[NN * DDIM];        // NORMALIZED aggregated msgs
static __device__ float g_x[NN * DDIM];          // residual stream
static __device__ float g_y[NN * DDIM];          // LN2 output
static __device__ int   g_deg[NN];               // per-dst degree
static __device__ int   g_off[NN + 1];           // CSR offsets
static __device__ int   g_pos[NN];               // scatter cursors
static __device__ int   g_eid[EE];               // edge ids grouped by dst
static __device__ int   g_bsum[NB];              // scan block partials

// ---------------- CSR build ----------------
__global__ void zero_deg_kernel() {
    int i = blockIdx.x * blockDim.x + threadIdx.x;
    if (i < NN) g_deg[i] = 0;
}
__global__ void hist_kernel(const int* __restrict__ dst) {
    int e = blockIdx.x * blockDim.x + threadIdx.x;
    if (e < EE) atomicAdd(&g_deg[dst[e]], 1);
}
__global__ void scanA_kernel() {
    __shared__ int sh[256];
    int t = threadIdx.x;
    int i = blockIdx.x * 256 + t;
    int val = (i < NN) ? g_deg[i] : 0;
    sh[t] = val;
    #pragma unroll
    for (int o = 1; o < 256; o <<= 1) {
        __syncthreads();
        int x = (t >= o) ? sh[t - o] : 0;
        __syncthreads();
        sh[t] += x;
    }
    __syncthreads();
    int excl = sh[t] - val;
    if (i < NN) g_off[i] = excl;
    if (t == 255) g_bsum[blockIdx.x] = sh[255];
}
__global__ void scanB_kernel() {
    __shared__ int sh[256];
    int t = threadIdx.x;
    int val = (t < NB) ? g_bsum[t] : 0;
    sh[t] = val;
    #pragma unroll
    for (int o = 1; o < 256; o <<= 1) {
        __syncthreads();
        int x = (t >= o) ? sh[t - o] : 0;
        __syncthreads();
        sh[t] += x;
    }
    __syncthreads();
    if (t < NB) g_bsum[t] = sh[t] - val;
}
__global__ void scanC_kernel() {
    int i = blockIdx.x * 256 + threadIdx.x;
    if (i < NN) {
        int v = g_off[i] + g_bsum[blockIdx.x];
        g_off[i] = v;
        g_pos[i] = v;
    }
    if (i == 0) g_off[NN] = EE;
}
__global__ void scatter_kernel(const int* __restrict__ dst) {
    int e = blockIdx.x * blockDim.x + threadIdx.x;
    if (e >= EE) return;
    int d = dst[e];
    int p = atomicAdd(&g_pos[d], 1);
    g_eid[p] = e;
}

// ---------------- fused attention: one warp per destination node ----------------
#define ALOAD(qv, vv, dd, idx) do {                                         \
    int e_ = g_eid[idx]; int s_ = src[e_];                                  \
    qv = *(const float4*)(g_qkv + (size_t)s_ * 384 + lane * 4);             \
    vv = *(const float4*)(g_qkv + (size_t)s_ * 384 + 256 + lane * 4);       \
    dd = dist[e_ * 8 + h] + path[e_ * 8 + h];                               \
} while (0)

#define ASTEP(qv, vv, dd) do {                                              \
    float dot = qv.x * kv.x + qv.y * kv.y + qv.z * kv.z + qv.w * kv.w;      \
    dot += __shfl_xor_sync(0xFFFFFFFFu, dot, 1);                            \
    dot += __shfl_xor_sync(0xFFFFFFFFu, dot, 2);                            \
    float a_ = dot + dd;                                                    \
    float mn_ = fmaxf(m, a_);                                               \
    float corr_ = __expf(m - mn_);                                          \
    float p_ = __expf(a_ - mn_);                                            \
    den = den * corr_ + p_;                                                 \
    acc.x = acc.x * corr_ + vv.x * p_;                                      \
    acc.y = acc.y * corr_ + vv.y * p_;                                      \
    acc.z = acc.z * corr_ + vv.z * p_;                                      \
    acc.w = acc.w * corr_ + vv.w * p_;                                      \
    m = mn_;                                                                \
} while (0)

__global__ void attn_kernel(const int* __restrict__ src,
                            const float* __restrict__ dist,
                            const float* __restrict__ path) {
    int w = (blockIdx.x * blockDim.x + threadIdx.x) >> 5;
    if (w >= NN) return;
    int lane = threadIdx.x & 31;
    int h = lane >> 2;  // 4 lanes per head, 16 dims/head
    int beg = g_off[w], end = g_off[w + 1];
    float4 kv = *(const float4*)(g_qkv + (size_t)w * 384 + 128 + lane * 4);
    float4 acc = make_float4(0.f, 0.f, 0.f, 0.f);
    float m = -1e30f, den = 0.f;
    int cnt = end - beg;

    if (cnt > 0) {
        float4 q0, v0, q1, v1;
        float d0 = 0.f, d1 = 0.f;
        ALOAD(q0, v0, d0, beg);
        if (cnt > 1) ALOAD(q1, v1, d1, beg + 1);
        int i = 0;
        while (i + 1 < cnt) {
            ASTEP(q0, v0, d0);
            if (i + 2 < cnt) ALOAD(q0, v0, d0, beg + i + 2);
            ASTEP(q1, v1, d1);
            if (i + 3 < cnt) ALOAD(q1, v1, d1, beg + i + 3);
            i += 2;
        }
        if (i < cnt) ASTEP(q0, v0, d0);  // odd tail lives in slot 0
    }
    float inv = (den > 0.f) ? (1.0f / den) : 0.f;
    acc.x *= inv; acc.y *= inv; acc.z *= inv; acc.w *= inv;
    *(float4*)(g_agg + (size_t)w * DDIM + lane * 4) = acc;
}

// ---------------- LayerNorm: one warp per row of 128 ----------------
__global__ void ln_kernel(const float* __restrict__ in,
                          const float* __restrict__ g,
                          const float* __restrict__ b,
                          float* __restrict__ out, int n) {
    int wid  = (blockIdx.x * blockDim.x + threadIdx.x) >> 5;
    int lane = threadIdx.x & 31;
    if (wid >= n) return;
    const float4* row = (const float4*)(in + (size_t)wid * DDIM);
    float4 x = row[lane];
    float s  = x.x + x.y + x.z + x.w;
    float s2 = x.x * x.x + x.y * x.y + x.z * x.z + x.w * x.w;
    #pragma unroll
    for (int o = 16; o > 0; o >>= 1) {
        s  += __shfl_xor_sync(0xFFFFFFFFu, s,  o);
        s2 += __shfl_xor_sync(0xFFFFFFFFu, s2, o);
    }
    float mu  = s  * (1.0f / 128.0f);
    float var = s2 * (1.0f / 128.0f) - mu * mu;
    float r   = rsqrtf(var + 1e-5f);
    float4 gg = ((const float4*)g)[lane];
    float4 bb = ((const float4*)b)[lane];
    float4 o4;
    o4.x = (x.x - mu) * r * gg.x + bb.x;
    o4.y = (x.y - mu) * r * gg.y + bb.y;
    o4.z = (x.z - mu) * r * gg.z + bb.z;
    o4.w = (x.w - mu) * r * gg.w + bb.w;
    ((float4*)(out + (size_t)wid * DDIM))[lane] = o4;
}

// ---------------- FP16 tensor-core GEMM (m16n8k16, fp32 accum) ----------------
// Block 128x128, K-tile 32, 8 warps (4x2), warp tile 32x64.
// As: halfs [128 rows][32 k], u32 stride SA=20 (read banks 4g+t, conflict-free)
// Bs: half2 k-pairs [16 k2][128 n], u32 stride SB=136 (read banks 8t+g, cf)
#define SA 20
#define SB 136
#define ABUF (128 * SA)   // 2560 u32
#define BBUF (16 * SB)    // 2176 u32
#define GM_SMEM ((2 * ABUF + 2 * BBUF) * 4)  // 37888 B

static __device__ __forceinline__ unsigned fh2(float lo, float hi) {
    __half2 hv = __floats2half2_rn(lo, hi);
    return *reinterpret_cast<unsigned*>(&hv);
}

#define MMA_F16(d, a, b0, b1)                                               \
    asm volatile("mma.sync.aligned.m16n8k16.row.col.f32.f16.f16.f32 "       \
                 "{%0,%1,%2,%3}, {%4,%5,%6,%7}, {%8,%9}, {%0,%1,%2,%3};"    \
                 : "+f"(d[0]), "+f"(d[1]), "+f"(d[2]), "+f"(d[3])           \
                 : "r"(a[0]), "r"(a[1]), "r"(a[2]), "r"(a[3]),              \
                   "r"(b0), "r"(b1))

static __device__ __forceinline__ float gelu_f(float v) {
    float t = tanhf(0.7978845608028654f * (v + 0.044715f * v * v * v));
    return 0.5f * v * (1.0f + t);
}

template <int EPI>
__global__ __launch_bounds__(256)
void gemm_tc(const float* __restrict__ A,
             const float* __restrict__ W,
             const float* __restrict__ bias,
             const float* __restrict__ res,
             float* __restrict__ C,
             int n, int M, int K) {
    extern __shared__ unsigned sm[];
    unsigned* As = sm;                  // 2 x ABUF
    unsigned* Bs = sm + 2 * ABUF;       // 2 x BBUF

    const int tid  = threadIdx.x;
    const int lane = tid & 31, warp = tid >> 5;
    const int lg = lane >> 2, lr = lane & 3;
    const int wm = warp & 3,  wn = warp >> 2;
    const int row0 = blockIdx.y * 128;
    const int col0 = blockIdx.x * 128;
    const int KT = K >> 5;

    float acc[2][8][4];
    #pragma unroll
    for (int mt = 0; mt < 2; mt++)
        #pragma unroll
        for (int nt = 0; nt < 8; nt++)
            #pragma unroll
            for (int i = 0; i < 4; i++) acc[mt][nt][i] = 0.f;

    float4 ra[4], rb0[2], rb1[2];

    // -------- prologue: load + store tile 0 --------
    #pragma unroll
    for (int j = 0; j < 4; j++) {
        int f = tid + j * 256;
        int r = f >> 3, kc = f & 7;
        float4 v = make_float4(0.f, 0.f, 0.f, 0.f);
        if (row0 + r < n)
            v = *(const float4*)(A + (size_t)(row0 + r) * K + kc * 4);
        ra[j] = v;
    }
    #pragma unroll
    for (int j = 0; j < 2; j++) {
        int f = tid + j * 256;
        int ng = f & 31, k2 = f >> 5;
        rb0[j] = *(const float4*)(W + (size_t)(k2 * 2) * M + col0 + ng * 4);
        rb1[j] = *(const float4*)(W + (size_t)(k2 * 2 + 1) * M + col0 + ng * 4);
    }
    #pragma unroll
    for (int j = 0; j < 4; j++) {
        int f = tid + j * 256;
        int r = f >> 3, kc = f & 7;
        *(uint2*)(As + r * SA + kc * 2) =
            make_uint2(fh2(ra[j].x, ra[j].y), fh2(ra[j].z, ra[j].w));
    }
    #pragma unroll
    for (int j = 0; j < 2; j++) {
        int f = tid + j * 256;
        int ng = f & 31, k2 = f >> 5;
        uint4 u;
        u.x = fh2(rb0[j].x, rb1[j].x);
        u.y = fh2(rb0[j].y, rb1[j].y);
        u.z = fh2(rb0[j].z, rb1[j].z);
        u.w = fh2(rb0[j].w, rb1[j].w);
        *(uint4*)(Bs + k2 * SB + ng * 4) = u;
    }
    __syncthreads();

    for (int kt = 0; kt < KT; kt++) {
        const int cur = kt & 1;
        if (kt + 1 < KT) {
            #pragma unroll
            for (int j = 0; j < 4; j++) {
                int f = tid + j * 256;
                int r = f >> 3, kc = f & 7;
                float4 v = make_float4(0.f, 0.f, 0.f, 0.f);
                if (row0 + r < n)
                    v = *(const float4*)(A + (size_t)(row0 + r) * K + (kt + 1) * 32 + kc * 4);
                ra[j] = v;
            }
            #pragma unroll
            for (int j = 0; j < 2; j++) {
                int f = tid + j * 256;
                int ng = f & 31, k2 = f >> 5;
                int kr = (kt + 1) * 32 + k2 * 2;
                rb0[j] = *(const float4*)(W + (size_t)kr * M + col0 + ng * 4);
                rb1[j] = *(const float4*)(W + (size_t)(kr + 1) * M + col0 + ng * 4);
            }
        }
        const unsigned* Ab = As + cur * ABUF;
        const unsigned* Bb = Bs + cur * BBUF;
        #pragma unroll
        for (int ks = 0; ks < 2; ks++) {
            unsigned a[2][4];
            #pragma unroll
            for (int mt = 0; mt < 2; mt++) {
                const unsigned* ap = Ab + (wm * 32 + mt * 16 + lg) * SA + ks * 8 + lr;
                a[mt][0] = ap[0];
                a[mt][1] = ap[8 * SA];
                a[mt][2] = ap[4];
                a[mt][3] = ap[8 * SA + 4];
            }
            #pragma unroll
            for (int nt = 0; nt < 8; nt++) {
                const unsigned* bp = Bb + (ks * 8 + lr) * SB + wn * 64 + nt * 8 + lg;
                unsigned b0 = bp[0];
                unsigned b1 = bp[4 * SB];
                MMA_F16(acc[0][nt], a[0], b0, b1);
                MMA_F16(acc[1][nt], a[1], b0, b1);
            }
        }
        if (kt + 1 < KT) {
            unsigned* Ad = As + (cur ^ 1) * ABUF;
            unsigned* Bd = Bs + (cur ^ 1) * BBUF;
            #pragma unroll
            for (int j = 0; j < 4; j++) {
                int f = tid + j * 256;
                int r = f >> 3, kc = f & 7;
                *(uint2*)(Ad + r * SA + kc * 2) =
                    make_uint2(fh2(ra[j].x, ra[j].y), fh2(ra[j].z, ra[j].w));
            }
            #pragma unroll
            for (int j = 0; j < 2; j++) {
                int f = tid + j * 256;
                int ng = f & 31, k2 = f >> 5;
                uint4 u;
                u.x = fh2(rb0[j].x, rb1[j].x);
                u.y = fh2(rb0[j].y, rb1[j].y);
                u.z = fh2(rb0[j].z, rb1[j].z);
                u.w = fh2(rb0[j].w, rb1[j].w);
                *(uint4*)(Bd + k2 * SB + ng * 4) = u;
            }
        }
        __syncthreads();
    }

    const float sc = 0.08838834764831845f;  // D^-0.5
    #pragma unroll
    for (int mt = 0; mt < 2; mt++) {
        #pragma unroll
        for (int nt = 0; nt < 8; nt++) {
            int r = row0 + wm * 32 + mt * 16 + lg;
            int c = col0 + wn * 64 + nt * 8 + lr * 2;
            float b0 = bias[c], b1 = bias[c + 1];
            float v0 = acc[mt][nt][0] + b0;
            float v1 = acc[mt][nt][1] + b1;
            float v2 = acc[mt][nt][2] + b0;
            float v3 = acc[mt][nt][3] + b1;
            if (EPI == 0) {
                if (blockIdx.x == 0) {
                    v0 *= sc; v1 *= sc; v2 *= sc; v3 *= sc;
                }
            }
            if (r < n) {
                float2 o = make_float2(v0, v1);
                if (EPI == 1) {
                    float2 rr = *(const float2*)(res + (size_t)r * M + c);
                    o.x += rr.x; o.y += rr.y;
                }
                *(float2*)(C + (size_t)r * M + c) = o;
            }
            if (r + 8 < n) {
                float2 o = make_float2(v2, v3);
                if (EPI == 1) {
                    float2 rr = *(const float2*)(res + (size_t)(r + 8) * M + c);
                    o.x += rr.x; o.y += rr.y;
                }
                *(float2*)(C + (size_t)(r + 8) * M + c) = o;
            }
        }
    }
}

// ---------------- fused MLP (fp16): out = res + gelu(Y@W1+b1)@W2 + b2 --------
#define SY 68                 // u32 stride for 128-half rows (banks 4g+t)
#define YBUF (128 * SY)       // 8704 u32
#define FM_SMEM ((2 * YBUF + 2 * BBUF) * 4)  // 87040 B

__global__ __launch_bounds__(256)
void fmlp_kernel(const float* __restrict__ Y,
                 const float* __restrict__ W1,
                 const float* __restrict__ b1,
                 const float* __restrict__ W2,
                 const float* __restrict__ b2,
                 const float* __restrict__ res,
                 float* __restrict__ C, int n) {
    extern __shared__ unsigned sm[];
    unsigned* Ys = sm;                 // 128 x SY
    unsigned* Hs = sm + YBUF;          // 128 x SY
    unsigned* Bs = sm + 2 * YBUF;      // 2 x BBUF

    const int tid  = threadIdx.x;
    const int lane = tid & 31, warp = tid >> 5;
    const int lg = lane >> 2, lr = lane & 3;
    const int wm = warp & 3,  wn = warp >> 2;
    const int row0 = blockIdx.x * 128;

    // stage Y tile (128 x 128) as fp16
    #pragma unroll
    for (int j = 0; j < 16; j++) {
        int f = tid + j * 256;
        int r = f >> 5, c4 = f & 31;
        float4 v = make_float4(0.f, 0.f, 0.f, 0.f);
        if (row0 + r < n)
            v = *(const float4*)(Y + (size_t)(row0 + r) * DDIM + c4 * 4);
        *(uint2*)(Ys + r * SY + c4 * 2) =
            make_uint2(fh2(v.x, v.y), fh2(v.z, v.w));
    }

    float acc2[2][8][4];
    #pragma unroll
    for (int mt = 0; mt < 2; mt++)
        #pragma unroll
        for (int nt = 0; nt < 8; nt++)
            #pragma unroll
            for (int i = 0; i < 4; i++) acc2[mt][nt][i] = 0.f;

    float4 rb0[2], rb1[2];
    __syncthreads();

    for (int cch = 0; cch < 4; cch++) {
        // ---- phase 1: H = Y @ W1[:, cch*128 .. +128] ----
        float acc[2][8][4];
        #pragma unroll
        for (int mt = 0; mt < 2; mt++)
            #pragma unroll
            for (int nt = 0; nt < 8; nt++)
                #pragma unroll
                for (int i = 0; i < 4; i++) acc[mt][nt][i] = 0.f;

        // stage W1 k-tile 0
        #pragma unroll
        for (int j = 0; j < 2; j++) {
            int f = tid + j * 256;
            int ng = f & 31, k2 = f >> 5;
            float4 w0 = *(const float4*)(W1 + (size_t)(k2 * 2) * 512 + cch * 128 + ng * 4);
            float4 w1 = *(const float4*)(W1 + (size_t)(k2 * 2 + 1) * 512 + cch * 128 + ng * 4);
            uint4 u;
            u.x = fh2(w0.x, w1.x); u.y = fh2(w0.y, w1.y);
            u.z = fh2(w0.z, w1.z); u.w = fh2(w0.w, w1.w);
            *(uint4*)(Bs + k2 * SB + ng * 4) = u;
        }
        __syncthreads();

        #pragma unroll
        for (int kt = 0; kt < 4; kt++) {
            const int cur = kt & 1;
            if (kt < 3) {
                #pragma unroll
                for (int j = 0; j < 2; j++) {
                    int f = tid + j * 256;
                    int ng = f & 31, k2 = f >> 5;
                    int kr = (kt + 1) * 32 + k2 * 2;
                    rb0[j] = *(const float4*)(W1 + (size_t)kr * 512 + cch * 128 + ng * 4);
                    rb1[j] = *(const float4*)(W1 + (size_t)(kr + 1) * 512 + cch * 128 + ng * 4);
                }
            }
            const unsigned* Bb = Bs + cur * BBUF;
            #pragma unroll
            for (int ks = 0; ks < 2; ks++) {
                unsigned a[2][4];
                #pragma unroll
                for (int mt = 0; mt < 2; mt++) {
                    const unsigned* ap = Ys + (wm * 32 + mt * 16 + lg) * SY + (kt * 2 + ks) * 8 + lr;
                    a[mt][0] = ap[0];
                    a[mt][1] = ap[8 * SY];
                    a[mt][2] = ap[4];
                    a[mt][3] = ap[8 * SY + 4];
                }
                #pragma unroll
                for (int nt = 0; nt < 8; nt++) {
                    const unsigned* bp = Bb + (ks * 8 + lr) * SB + wn * 64 + nt * 8 + lg;
                    unsigned b0 = bp[0];
                    unsigned b1v = bp[4 * SB];
                    MMA_F16(acc[0][nt], a[0], b0, b1v);
                    MMA_F16(acc[1][nt], a[1], b0, b1v);
                }
            }
            if (kt < 3) {
                unsigned* Bd = Bs + (cur ^ 1) * BBUF;
                #pragma unroll
                for (int j = 0; j < 2; j++) {
                    int f = tid + j * 256;
                    int ng = f & 31, k2 = f >> 5;
                    uint4 u;
                    u.x = fh2(rb0[j].x, rb1[j].x); u.y = fh2(rb0[j].y, rb1[j].y);
                    u.z = fh2(rb0[j].z, rb1[j].z); u.w = fh2(rb0[j].w, rb1[j].w);
                    *(uint4*)(Bd + k2 * SB + ng * 4) = u;
                }
            }
            __syncthreads();
        }

        // gelu + b1 -> Hs (fp16)
        #pragma unroll
        for (int mt = 0; mt < 2; mt++) {
            #pragma unroll
            for (int nt = 0; nt < 8; nt++) {
                int rloc = wm * 32 + mt * 16 + lg;
                int cu = wn * 32 + nt * 4 + lr;   // u32 column index
                float bb0 = b1[cch * 128 + cu * 2];
                float bb1 = b1[cch * 128 + cu * 2 + 1];
                Hs[rloc * SY + cu] =
                    fh2(gelu_f(acc[mt][nt][0] + bb0), gelu_f(acc[mt][nt][1] + bb1));
                Hs[(rloc + 8) * SY + cu] =
                    fh2(gelu_f(acc[mt][nt][2] + bb0), gelu_f(acc[mt][nt][3] + bb1));
            }
        }
        __syncthreads();

        // ---- phase 2: acc2 += H @ W2[cch*128 .. +128, :] ----
        #pragma unroll
        for (int j = 0; j < 2; j++) {
            int f = tid + j * 256;
            int ng = f & 31, k2 = f >> 5;
            float4 w0 = *(const float4*)(W2 + (size_t)(cch * 128 + k2 * 2) * DDIM + ng * 4);
            float4 w1 = *(const float4*)(W2 + (size_t)(cch * 128 + k2 * 2 + 1) * DDIM + ng * 4);
            uint4 u;
            u.x = fh2(w0.x, w1.x); u.y = fh2(w0.y, w1.y);
            u.z = fh2(w0.z, w1.z); u.w = fh2(w0.w, w1.w);
            *(uint4*)(Bs + k2 * SB + ng * 4) = u;
        }
        __syncthreads();

        #pragma unroll
        for (int kt = 0; kt < 4; kt++) {
            const int cur = kt & 1;
            if (kt < 3) {
                #pragma unroll
                for (int j = 0; j < 2; j++) {
                    int f = tid + j * 256;
                    int ng = f & 31, k2 = f >> 5;
                    int kr = cch * 128 + (kt + 1) * 32 + k2 * 2;
                    rb0[j] = *(const float4*)(W2 + (size_t)kr * DDIM + ng * 4);
                    rb1[j] = *(const float4*)(W2 + (size_t)(kr + 1) * DDIM + ng * 4);
                }
            }
            const unsigned* Bb = Bs + cur * BBUF;
            #pragma unroll
            for (int ks = 0; ks < 2; ks++) {
                unsigned a[2][4];
                #pragma unroll
                for (int mt = 0; mt < 2; mt++) {
                    const unsigned* ap = Hs + (wm * 32 + mt * 16 + lg) * SY + (kt * 2 + ks) * 8 + lr;
                    a[mt][0] = ap[0];
                    a[mt][1] = ap[8 * SY];
                    a[mt][2] = ap[4];
                    a[mt][3] = ap[8 * SY + 4];
                }
                #pragma unroll
                for (int nt = 0; nt < 8; nt++) {
                    const unsigned* bp = Bb + (ks * 8 + lr) * SB + wn * 64 + nt * 8 + lg;
                    unsigned b0 = bp[0];
                    unsigned b1v = bp[4 * SB];
                    MMA_F16(acc2[0][nt], a[0], b0, b1v);
                    MMA_F16(acc2[1][nt], a[1], b0, b1v);
                }
            }
            if (kt < 3) {
                unsigned* Bd = Bs + (cur ^ 1) * BBUF;
                #pragma unroll
                for (int j = 0; j < 2; j++) {
                    int f = tid + j * 256;
                    int ng = f & 31, k2 = f >> 5;
                    uint4 u;
                    u.x = fh2(rb0[j].x, rb1[j].x); u.y = fh2(rb0[j].y, rb1[j].y);
                    u.z = fh2(rb0[j].z, rb1[j].z); u.w = fh2(rb0[j].w, rb1[j].w);
                    *(uint4*)(Bd + k2 * SB + ng * 4) = u;
                }
            }
            __syncthreads();
        }
    }

    // epilogue: + b2 + res
    #pragma unroll
    for (int mt = 0; mt < 2; mt++) {
        #pragma unroll
        for (int nt = 0; nt < 8; nt++) {
            int r = row0 + wm * 32 + mt * 16 + lg;
            int c = wn * 64 + nt * 8 + lr * 2;
            float bb0 = b2[c], bb1 = b2[c + 1];
            if (r < n) {
                float2 rr = *(const float2*)(res + (size_t)r * DDIM + c);
                float2 o = make_float2(acc2[mt][nt][0] + bb0 + rr.x,
                                       acc2[mt][nt][1] + bb1 + rr.y);
                *(float2*)(C + (size_t)r * DDIM + c) = o;
            }
            if (r + 8 < n) {
                float2 rr = *(const float2*)(res + (size_t)(r + 8) * DDIM + c);
                float2 o = make_float2(acc2[mt][nt][2] + bb0 + rr.x,
                                       acc2[mt][nt][3] + bb1 + rr.y);
                *(float2*)(C + (size_t)(r + 8) * DDIM + c) = o;
            }
        }
    }
}

// ---------------- launch ----------------
extern "C" void kernel_launch(void* const* d_in, const int* in_sizes, int n_in,
                              void* d_out, int out_size) {
    const float* node_feature = (const float*)d_in[0];
    const float* dist_attn    = (const float*)d_in[1];
    const float* path_attn    = (const float*)d_in[2];
    const int*   src          = (const int*)d_in[3];
    const int*   dst          = (const int*)d_in[4];
    const float* ln1_g        = (const float*)d_in[5];
    const float* ln1_b        = (const float*)d_in[6];
    const float* qkv_w        = (const float*)d_in[7];
    const float* qkv_b        = (const float*)d_in[8];
    const float* in_proj_w    = (const float*)d_in[9];
    const float* in_proj_b    = (const float*)d_in[10];
    const float* res_ln_g     = (const float*)d_in[11];
    const float* res_ln_b     = (const float*)d_in[12];
    const float* mlp_w1       = (const float*)d_in[13];
    const float* mlp_b1       = (const float*)d_in[14];
    const float* mlp_w2       = (const float*)d_in[15];
    const float* mlp_b2       = (const float*)d_in[16];
    float* out = (float*)d_out;

    cudaFuncSetAttribute(gemm_tc<0>, cudaFuncAttributeMaxDynamicSharedMemorySize, GM_SMEM);
    cudaFuncSetAttribute(gemm_tc<1>, cudaFuncAttributeMaxDynamicSharedMemorySize, GM_SMEM);
    cudaFuncSetAttribute(fmlp_kernel, cudaFuncAttributeMaxDynamicSharedMemorySize, FM_SMEM);

    void* p;
    cudaGetSymbolAddress(&p, g_h);    float* ph   = (float*)p;
    cudaGetSymbolAddress(&p, g_qkv);  float* pqkv = (float*)p;
    cudaGetSymbolAddress(&p, g_agg);  float* pagg = (float*)p;
    cudaGetSymbolAddress(&p, g_x);    float* px   = (float*)p;
    cudaGetSymbolAddress(&p, g_y);    float* py   = (float*)p;

    const int RB = (NN + 127) / 128;           // 391 row blocks
    const int LN_BLOCKS = (NN + 7) / 8;
    const int E_BLOCKS  = (EE + 255) / 256;
    const int N_BLOCKS  = (NN + 255) / 256;    // == NB
    const int ATTN_BLOCKS = (NN * 32 + 255) / 256;

    // CSR build
    zero_deg_kernel<<<N_BLOCKS, 256>>>();
    hist_kernel<<<E_BLOCKS, 256>>>(dst);
    scanA_kernel<<<NB, 256>>>();
    scanB_kernel<<<1, 256>>>();
    scanC_kernel<<<NB, 256>>>();
    scatter_kernel<<<E_BLOCKS, 256>>>(dst);

    // main pipeline
    ln_kernel<<<LN_BLOCKS, 256>>>(node_feature, ln1_g, ln1_b, ph, NN);
    gemm_tc<0><<<dim3(3, RB), 256, GM_SMEM>>>(ph, qkv_w, qkv_b, nullptr, pqkv, NN, 384, 128);
    attn_kernel<<<ATTN_BLOCKS, 256>>>(src, dist_attn, path_attn);
    gemm_tc<1><<<dim3(1, RB), 256, GM_SMEM>>>(pagg, in_proj_w, in_proj_b, ph, px, NN, 128, 128);
    ln_kernel<<<LN_BLOCKS, 256>>>(px, res_ln_g, res_ln_b, py, NN);
    fmlp_kernel<<<RB, 256, FM_SMEM>>>(py, mlp_w1, mlp_b1, mlp_w2, mlp_b2, px, out, NN);
}

// round 10
// speedup vs baseline: 2.9362x; 1.0474x over previous
#include <cuda_runtime.h>
#include <cuda_fp16.h>
#include <math.h>

#define NN 50000
#define EE 600000
#define DDIM 128
#define HH 8
#define NB 196   // ceil(NN/256) scan blocks

// ---------------- scratch (static device memory; no allocs) ----------------
static __device__ float  g_h[NN * DDIM];           // LN1 output (float, residual)
static __device__ __half g_hh[NN * DDIM];          // LN1 output (half, GEMM A)
static __device__ __half g_qkv[NN * 3 * DDIM];     // [N][3][H][16] half
static __device__ float  g_agg[NN * DDIM];         // aggregated msgs (float)
static __device__ float  g_x[NN * DDIM];           // residual stream
static __device__ __half g_yh[NN * DDIM];          // LN2 output (half)
static __device__ int    g_deg[NN];
static __device__ int    g_off[NN + 1];
static __device__ int    g_pos[NN];
static __device__ int    g_eid[EE];
static __device__ int    g_bsum[NB];

// ---------------- CSR build ----------------
__global__ void zero_deg_kernel() {
    int i = blockIdx.x * blockDim.x + threadIdx.x;
    if (i < NN) g_deg[i] = 0;
}
__global__ void hist_kernel(const int* __restrict__ dst) {
    int e = blockIdx.x * blockDim.x + threadIdx.x;
    if (e < EE) atomicAdd(&g_deg[dst[e]], 1);
}
__global__ void scanA_kernel() {
    __shared__ int sh[256];
    int t = threadIdx.x;
    int i = blockIdx.x * 256 + t;
    int val = (i < NN) ? g_deg[i] : 0;
    sh[t] = val;
    #pragma unroll
    for (int o = 1; o < 256; o <<= 1) {
        __syncthreads();
        int x = (t >= o) ? sh[t - o] : 0;
        __syncthreads();
        sh[t] += x;
    }
    __syncthreads();
    int excl = sh[t] - val;
    if (i < NN) g_off[i] = excl;
    if (t == 255) g_bsum[blockIdx.x] = sh[255];
}
// merged scanB+scanC: each block reduces its own prefix of g_bsum
__global__ void scanBC_kernel() {
    __shared__ int sh[256];
    int t = threadIdx.x;
    sh[t] = (t < blockIdx.x && t < NB) ? g_bsum[t] : 0;
    __syncthreads();
    #pragma unroll
    for (int o = 128; o > 0; o >>= 1) {
        if (t < o) sh[t] += sh[t + o];
        __syncthreads();
    }
    int base = sh[0];
    int i = blockIdx.x * 256 + t;
    if (i < NN) {
        int v = g_off[i] + base;
        g_off[i] = v;
        g_pos[i] = v;
    }
    if (i == 0) g_off[NN] = EE;
}
__global__ void scatter_kernel(const int* __restrict__ dst) {
    int e = blockIdx.x * blockDim.x + threadIdx.x;
    if (e >= EE) return;
    int d = dst[e];
    int p = atomicAdd(&g_pos[d], 1);
    g_eid[p] = e;
}

// ---------------- fused attention: one warp per destination node ----------------
static __device__ __forceinline__ float4 ldqkv_h4(const __half* p) {
    uint2 u = *(const uint2*)p;
    float2 a = __half22float2(*reinterpret_cast<__half2*>(&u.x));
    float2 b = __half22float2(*reinterpret_cast<__half2*>(&u.y));
    return make_float4(a.x, a.y, b.x, b.y);
}

#define ALOAD(qv, vv, dd, idx) do {                                         \
    int e_ = g_eid[idx]; int s_ = src[e_];                                  \
    qv = ldqkv_h4(g_qkv + (size_t)s_ * 384 + lane * 4);                     \
    vv = ldqkv_h4(g_qkv + (size_t)s_ * 384 + 256 + lane * 4);               \
    dd = dist[e_ * 8 + h] + path[e_ * 8 + h];                               \
} while (0)

#define ASTEP(qv, vv, dd) do {                                              \
    float dot = qv.x * kv.x + qv.y * kv.y + qv.z * kv.z + qv.w * kv.w;      \
    dot += __shfl_xor_sync(0xFFFFFFFFu, dot, 1);                            \
    dot += __shfl_xor_sync(0xFFFFFFFFu, dot, 2);                            \
    float a_ = dot + dd;                                                    \
    float mn_ = fmaxf(m, a_);                                               \
    float corr_ = __expf(m - mn_);                                          \
    float p_ = __expf(a_ - mn_);                                            \
    den = den * corr_ + p_;                                                 \
    acc.x = acc.x * corr_ + vv.x * p_;                                      \
    acc.y = acc.y * corr_ + vv.y * p_;                                      \
    acc.z = acc.z * corr_ + vv.z * p_;                                      \
    acc.w = acc.w * corr_ + vv.w * p_;                                      \
    m = mn_;                                                                \
} while (0)

__global__ void attn_kernel(const int* __restrict__ src,
                            const float* __restrict__ dist,
                            const float* __restrict__ path) {
    int w = (blockIdx.x * blockDim.x + threadIdx.x) >> 5;
    if (w >= NN) return;
    int lane = threadIdx.x & 31;
    int h = lane >> 2;  // 4 lanes per head, 16 dims/head
    int beg = g_off[w], end = g_off[w + 1];
    float4 kv = ldqkv_h4(g_qkv + (size_t)w * 384 + 128 + lane * 4);
    float4 acc = make_float4(0.f, 0.f, 0.f, 0.f);
    float m = -1e30f, den = 0.f;
    int cnt = end - beg;

    if (cnt > 0) {
        float4 q0, v0, q1, v1;
        float d0 = 0.f, d1 = 0.f;
        ALOAD(q0, v0, d0, beg);
        if (cnt > 1) ALOAD(q1, v1, d1, beg + 1);
        int i = 0;
        while (i + 1 < cnt) {
            ASTEP(q0, v0, d0);
            if (i + 2 < cnt) ALOAD(q0, v0, d0, beg + i + 2);
            ASTEP(q1, v1, d1);
            if (i + 3 < cnt) ALOAD(q1, v1, d1, beg + i + 3);
            i += 2;
        }
        if (i < cnt) ASTEP(q0, v0, d0);  // odd tail lives in slot 0
    }
    float inv = (den > 0.f) ? (1.0f / den) : 0.f;
    acc.x *= inv; acc.y *= inv; acc.z *= inv; acc.w *= inv;
    *(float4*)(g_agg + (size_t)w * DDIM + lane * 4) = acc;
}

// ---------------- half pack helper ----------------
static __device__ __forceinline__ unsigned fh2(float lo, float hi) {
    __half2 hv = __floats2half2_rn(lo, hi);
    return *reinterpret_cast<unsigned*>(&hv);
}

// ---------------- LayerNorm: one warp per row; dual float/half output ----------
__global__ void ln_kernel(const float* __restrict__ in,
                          const float* __restrict__ g,
                          const float* __restrict__ b,
                          float* __restrict__ outf,
                          __half* __restrict__ outh, int n) {
    int wid  = (blockIdx.x * blockDim.x + threadIdx.x) >> 5;
    int lane = threadIdx.x & 31;
    if (wid >= n) return;
    const float4* row = (const float4*)(in + (size_t)wid * DDIM);
    float4 x = row[lane];
    float s  = x.x + x.y + x.z + x.w;
    float s2 = x.x * x.x + x.y * x.y + x.z * x.z + x.w * x.w;
    #pragma unroll
    for (int o = 16; o > 0; o >>= 1) {
        s  += __shfl_xor_sync(0xFFFFFFFFu, s,  o);
        s2 += __shfl_xor_sync(0xFFFFFFFFu, s2, o);
    }
    float mu  = s  * (1.0f / 128.0f);
    float var = s2 * (1.0f / 128.0f) - mu * mu;
    float r   = rsqrtf(var + 1e-5f);
    float4 gg = ((const float4*)g)[lane];
    float4 bb = ((const float4*)b)[lane];
    float4 o4;
    o4.x = (x.x - mu) * r * gg.x + bb.x;
    o4.y = (x.y - mu) * r * gg.y + bb.y;
    o4.z = (x.z - mu) * r * gg.z + bb.z;
    o4.w = (x.w - mu) * r * gg.w + bb.w;
    if (outf)
        ((float4*)(outf + (size_t)wid * DDIM))[lane] = o4;
    if (outh)
        *(uint2*)(outh + (size_t)wid * DDIM + lane * 4) =
            make_uint2(fh2(o4.x, o4.y), fh2(o4.z, o4.w));
}

// ---------------- FP16 tensor-core GEMM (m16n8k16, fp32 accum) ----------------
// Block 128x128, K-tile 32, 8 warps (4x2), warp tile 32x64.
// AHALF=1: A is __half (zero-conversion staging). EPI==0 writes half C (qkv),
// EPI==1 writes float C with residual add.
#define SA 20
#define SB 136
#define ABUF (128 * SA)   // 2560 u32
#define BBUF (16 * SB)    // 2176 u32
#define GM_SMEM ((2 * ABUF + 2 * BBUF) * 4)  // 37888 B

#define MMA_F16(d, a, b0, b1)                                               \
    asm volatile("mma.sync.aligned.m16n8k16.row.col.f32.f16.f16.f32 "       \
                 "{%0,%1,%2,%3}, {%4,%5,%6,%7}, {%8,%9}, {%0,%1,%2,%3};"    \
                 : "+f"(d[0]), "+f"(d[1]), "+f"(d[2]), "+f"(d[3])           \
                 : "r"(a[0]), "r"(a[1]), "r"(a[2]), "r"(a[3]),              \
                   "r"(b0), "r"(b1))

static __device__ __forceinline__ float gelu_f(float v) {
    float t = tanhf(0.7978845608028654f * (v + 0.044715f * v * v * v));
    return 0.5f * v * (1.0f + t);
}

template <int EPI, int AHALF>
__global__ __launch_bounds__(256)
void gemm_tc(const void* __restrict__ Av,
             const float* __restrict__ W,
             const float* __restrict__ bias,
             const float* __restrict__ res,
             void* __restrict__ Cv,
             int n, int M, int K) {
    extern __shared__ unsigned sm[];
    unsigned* As = sm;                  // 2 x ABUF
    unsigned* Bs = sm + 2 * ABUF;       // 2 x BBUF

    const int tid  = threadIdx.x;
    const int lane = tid & 31, warp = tid >> 5;
    const int lg = lane >> 2, lr = lane & 3;
    const int wm = warp & 3,  wn = warp >> 2;
    const int row0 = blockIdx.y * 128;
    const int col0 = blockIdx.x * 128;
    const int KT = K >> 5;

    float acc[2][8][4];
    #pragma unroll
    for (int mt = 0; mt < 2; mt++)
        #pragma unroll
        for (int nt = 0; nt < 8; nt++)
            #pragma unroll
            for (int i = 0; i < 4; i++) acc[mt][nt][i] = 0.f;

    float4 raf[4];
    uint2  rah[4];
    float4 rb0[2], rb1[2];

    // -------- prologue: load + store tile 0 --------
    #pragma unroll
    for (int j = 0; j < 4; j++) {
        int f = tid + j * 256;
        int r = f >> 3, kc = f & 7;
        if (AHALF) {
            const __half* A = (const __half*)Av;
            uint2 v = make_uint2(0u, 0u);
            if (row0 + r < n)
                v = *(const uint2*)(A + (size_t)(row0 + r) * K + kc * 4);
            rah[j] = v;
        } else {
            const float* A = (const float*)Av;
            float4 v = make_float4(0.f, 0.f, 0.f, 0.f);
            if (row0 + r < n)
                v = *(const float4*)(A + (size_t)(row0 + r) * K + kc * 4);
            raf[j] = v;
        }
    }
    #pragma unroll
    for (int j = 0; j < 2; j++) {
        int f = tid + j * 256;
        int ng = f & 31, k2 = f >> 5;
        rb0[j] = *(const float4*)(W + (size_t)(k2 * 2) * M + col0 + ng * 4);
        rb1[j] = *(const float4*)(W + (size_t)(k2 * 2 + 1) * M + col0 + ng * 4);
    }
    #pragma unroll
    for (int j = 0; j < 4; j++) {
        int f = tid + j * 256;
        int r = f >> 3, kc = f & 7;
        if (AHALF)
            *(uint2*)(As + r * SA + kc * 2) = rah[j];
        else
            *(uint2*)(As + r * SA + kc * 2) =
                make_uint2(fh2(raf[j].x, raf[j].y), fh2(raf[j].z, raf[j].w));
    }
    #pragma unroll
    for (int j = 0; j < 2; j++) {
        int f = tid + j * 256;
        int ng = f & 31, k2 = f >> 5;
        uint4 u;
        u.x = fh2(rb0[j].x, rb1[j].x);
        u.y = fh2(rb0[j].y, rb1[j].y);
        u.z = fh2(rb0[j].z, rb1[j].z);
        u.w = fh2(rb0[j].w, rb1[j].w);
        *(uint4*)(Bs + k2 * SB + ng * 4) = u;
    }
    __syncthreads();

    for (int kt = 0; kt < KT; kt++) {
        const int cur = kt & 1;
        if (kt + 1 < KT) {
            #pragma unroll
            for (int j = 0; j < 4; j++) {
                int f = tid + j * 256;
                int r = f >> 3, kc = f & 7;
                if (AHALF) {
                    const __half* A = (const __half*)Av;
                    uint2 v = make_uint2(0u, 0u);
                    if (row0 + r < n)
                        v = *(const uint2*)(A + (size_t)(row0 + r) * K + (kt + 1) * 32 + kc * 4);
                    rah[j] = v;
                } else {
                    const float* A = (const float*)Av;
                    float4 v = make_float4(0.f, 0.f, 0.f, 0.f);
                    if (row0 + r < n)
                        v = *(const float4*)(A + (size_t)(row0 + r) * K + (kt + 1) * 32 + kc * 4);
                    raf[j] = v;
                }
            }
            #pragma unroll
            for (int j = 0; j < 2; j++) {
                int f = tid + j * 256;
                int ng = f & 31, k2 = f >> 5;
                int kr = (kt + 1) * 32 + k2 * 2;
                rb0[j] = *(const float4*)(W + (size_t)kr * M + col0 + ng * 4);
                rb1[j] = *(const float4*)(W + (size_t)(kr + 1) * M + col0 + ng * 4);
            }
        }
        const unsigned* Ab = As + cur * ABUF;
        const unsigned* Bb = Bs + cur * BBUF;
        #pragma unroll
        for (int ks = 0; ks < 2; ks++) {
            unsigned a[2][4];
            #pragma unroll
            for (int mt = 0; mt < 2; mt++) {
                const unsigned* ap = Ab + (wm * 32 + mt * 16 + lg) * SA + ks * 8 + lr;
                a[mt][0] = ap[0];
                a[mt][1] = ap[8 * SA];
                a[mt][2] = ap[4];
                a[mt][3] = ap[8 * SA + 4];
            }
            #pragma unroll
            for (int nt = 0; nt < 8; nt++) {
                const unsigned* bp = Bb + (ks * 8 + lr) * SB + wn * 64 + nt * 8 + lg;
                unsigned b0 = bp[0];
                unsigned b1 = bp[4 * SB];
                MMA_F16(acc[0][nt], a[0], b0, b1);
                MMA_F16(acc[1][nt], a[1], b0, b1);
            }
        }
        if (kt + 1 < KT) {
            unsigned* Ad = As + (cur ^ 1) * ABUF;
            unsigned* Bd = Bs + (cur ^ 1) * BBUF;
            #pragma unroll
            for (int j = 0; j < 4; j++) {
                int f = tid + j * 256;
                int r = f >> 3, kc = f & 7;
                if (AHALF)
                    *(uint2*)(Ad + r * SA + kc * 2) = rah[j];
                else
                    *(uint2*)(Ad + r * SA + kc * 2) =
                        make_uint2(fh2(raf[j].x, raf[j].y), fh2(raf[j].z, raf[j].w));
            }
            #pragma unroll
            for (int j = 0; j < 2; j++) {
                int f = tid + j * 256;
                int ng = f & 31, k2 = f >> 5;
                uint4 u;
                u.x = fh2(rb0[j].x, rb1[j].x);
                u.y = fh2(rb0[j].y, rb1[j].y);
                u.z = fh2(rb0[j].z, rb1[j].z);
                u.w = fh2(rb0[j].w, rb1[j].w);
                *(uint4*)(Bd + k2 * SB + ng * 4) = u;
            }
        }
        __syncthreads();
    }

    const float sc = 0.08838834764831845f;  // D^-0.5
    #pragma unroll
    for (int mt = 0; mt < 2; mt++) {
        #pragma unroll
        for (int nt = 0; nt < 8; nt++) {
            int r = row0 + wm * 32 + mt * 16 + lg;
            int c = col0 + wn * 64 + nt * 8 + lr * 2;
            float b0 = bias[c], b1 = bias[c + 1];
            float v0 = acc[mt][nt][0] + b0;
            float v1 = acc[mt][nt][1] + b1;
            float v2 = acc[mt][nt][2] + b0;
            float v3 = acc[mt][nt][3] + b1;
            if (EPI == 0) {
                if (blockIdx.x == 0) {  // q columns
                    v0 *= sc; v1 *= sc; v2 *= sc; v3 *= sc;
                }
                __half* C = (__half*)Cv;
                if (r < n)
                    *(__half2*)(C + (size_t)r * M + c) = __floats2half2_rn(v0, v1);
                if (r + 8 < n)
                    *(__half2*)(C + (size_t)(r + 8) * M + c) = __floats2half2_rn(v2, v3);
            } else {
                float* C = (float*)Cv;
                if (r < n) {
                    float2 rr = *(const float2*)(res + (size_t)r * M + c);
                    *(float2*)(C + (size_t)r * M + c) =
                        make_float2(v0 + rr.x, v1 + rr.y);
                }
                if (r + 8 < n) {
                    float2 rr = *(const float2*)(res + (size_t)(r + 8) * M + c);
                    *(float2*)(C + (size_t)(r + 8) * M + c) =
                        make_float2(v2 + rr.x, v3 + rr.y);
                }
            }
        }
    }
}

// ---------------- fused MLP (fp16 in): out = res + gelu(Y@W1+b1)@W2 + b2 -----
#define SY 68                 // u32 stride for 128-half rows
#define YBUF (128 * SY)
#define FM_SMEM ((2 * YBUF + 2 * BBUF) * 4)  // 87040 B

__global__ __launch_bounds__(256)
void fmlp_kernel(const __half* __restrict__ Y,
                 const float* __restrict__ W1,
                 const float* __restrict__ b1,
                 const float* __restrict__ W2,
                 const float* __restrict__ b2,
                 const float* __restrict__ res,
                 float* __restrict__ C, int n) {
    extern __shared__ unsigned sm[];
    unsigned* Ys = sm;                 // 128 x SY
    unsigned* Hs = sm + YBUF;          // 128 x SY
    unsigned* Bs = sm + 2 * YBUF;      // 2 x BBUF

    const int tid  = threadIdx.x;
    const int lane = tid & 31, warp = tid >> 5;
    const int lg = lane >> 2, lr = lane & 3;
    const int wm = warp & 3,  wn = warp >> 2;
    const int row0 = blockIdx.x * 128;

    // stage Y tile (128 x 128 halves) zero-conversion
    #pragma unroll
    for (int j = 0; j < 16; j++) {
        int f = tid + j * 256;
        int r = f >> 5, c4 = f & 31;
        uint2 v = make_uint2(0u, 0u);
        if (row0 + r < n)
            v = *(const uint2*)(Y + (size_t)(row0 + r) * DDIM + c4 * 4);
        *(uint2*)(Ys + r * SY + c4 * 2) = v;
    }

    float acc2[2][8][4];
    #pragma unroll
    for (int mt = 0; mt < 2; mt++)
        #pragma unroll
        for (int nt = 0; nt < 8; nt++)
            #pragma unroll
            for (int i = 0; i < 4; i++) acc2[mt][nt][i] = 0.f;

    float4 rb0[2], rb1[2];
    __syncthreads();

    for (int cch = 0; cch < 4; cch++) {
        // ---- phase 1: H = Y @ W1[:, cch*128 .. +128] ----
        float acc[2][8][4];
        #pragma unroll
        for (int mt = 0; mt < 2; mt++)
            #pragma unroll
            for (int nt = 0; nt < 8; nt++)
                #pragma unroll
                for (int i = 0; i < 4; i++) acc[mt][nt][i] = 0.f;

        #pragma unroll
        for (int j = 0; j < 2; j++) {
            int f = tid + j * 256;
            int ng = f & 31, k2 = f >> 5;
            float4 w0 = *(const float4*)(W1 + (size_t)(k2 * 2) * 512 + cch * 128 + ng * 4);
            float4 w1 = *(const float4*)(W1 + (size_t)(k2 * 2 + 1) * 512 + cch * 128 + ng * 4);
            uint4 u;
            u.x = fh2(w0.x, w1.x); u.y = fh2(w0.y, w1.y);
            u.z = fh2(w0.z, w1.z); u.w = fh2(w0.w, w1.w);
            *(uint4*)(Bs + k2 * SB + ng * 4) = u;
        }
        __syncthreads();

        #pragma unroll
        for (int kt = 0; kt < 4; kt++) {
            const int cur = kt & 1;
            if (kt < 3) {
                #pragma unroll
                for (int j = 0; j < 2; j++) {
                    int f = tid + j * 256;
                    int ng = f & 31, k2 = f >> 5;
                    int kr = (kt + 1) * 32 + k2 * 2;
                    rb0[j] = *(const float4*)(W1 + (size_t)kr * 512 + cch * 128 + ng * 4);
                    rb1[j] = *(const float4*)(W1 + (size_t)(kr + 1) * 512 + cch * 128 + ng * 4);
                }
            }
            const unsigned* Bb = Bs + cur * BBUF;
            #pragma unroll
            for (int ks = 0; ks < 2; ks++) {
                unsigned a[2][4];
                #pragma unroll
                for (int mt = 0; mt < 2; mt++) {
                    const unsigned* ap = Ys + (wm * 32 + mt * 16 + lg) * SY + (kt * 2 + ks) * 8 + lr;
                    a[mt][0] = ap[0];
                    a[mt][1] = ap[8 * SY];
                    a[mt][2] = ap[4];
                    a[mt][3] = ap[8 * SY + 4];
                }
                #pragma unroll
                for (int nt = 0; nt < 8; nt++) {
                    const unsigned* bp = Bb + (ks * 8 + lr) * SB + wn * 64 + nt * 8 + lg;
                    unsigned b0 = bp[0];
                    unsigned b1v = bp[4 * SB];
                    MMA_F16(acc[0][nt], a[0], b0, b1v);
                    MMA_F16(acc[1][nt], a[1], b0, b1v);
                }
            }
            if (kt < 3) {
                unsigned* Bd = Bs + (cur ^ 1) * BBUF;
                #pragma unroll
                for (int j = 0; j < 2; j++) {
                    int f = tid + j * 256;
                    int ng = f & 31, k2 = f >> 5;
                    uint4 u;
                    u.x = fh2(rb0[j].x, rb1[j].x); u.y = fh2(rb0[j].y, rb1[j].y);
                    u.z = fh2(rb0[j].z, rb1[j].z); u.w = fh2(rb0[j].w, rb1[j].w);
                    *(uint4*)(Bd + k2 * SB + ng * 4) = u;
                }
            }
            __syncthreads();
        }

        // gelu + b1 -> Hs (fp16)
        #pragma unroll
        for (int mt = 0; mt < 2; mt++) {
            #pragma unroll
            for (int nt = 0; nt < 8; nt++) {
                int rloc = wm * 32 + mt * 16 + lg;
                int cu = wn * 32 + nt * 4 + lr;   // u32 column index
                float bb0 = b1[cch * 128 + cu * 2];
                float bb1 = b1[cch * 128 + cu * 2 + 1];
                Hs[rloc * SY + cu] =
                    fh2(gelu_f(acc[mt][nt][0] + bb0), gelu_f(acc[mt][nt][1] + bb1));
                Hs[(rloc + 8) * SY + cu] =
                    fh2(gelu_f(acc[mt][nt][2] + bb0), gelu_f(acc[mt][nt][3] + bb1));
            }
        }
        __syncthreads();

        // ---- phase 2: acc2 += H @ W2[cch*128 .. +128, :] ----
        #pragma unroll
        for (int j = 0; j < 2; j++) {
            int f = tid + j * 256;
            int ng = f & 31, k2 = f >> 5;
            float4 w0 = *(const float4*)(W2 + (size_t)(cch * 128 + k2 * 2) * DDIM + ng * 4);
            float4 w1 = *(const float4*)(W2 + (size_t)(cch * 128 + k2 * 2 + 1) * DDIM + ng * 4);
            uint4 u;
            u.x = fh2(w0.x, w1.x); u.y = fh2(w0.y, w1.y);
            u.z = fh2(w0.z, w1.z); u.w = fh2(w0.w, w1.w);
            *(uint4*)(Bs + k2 * SB + ng * 4) = u;
        }
        __syncthreads();

        #pragma unroll
        for (int kt = 0; kt < 4; kt++) {
            const int cur = kt & 1;
            if (kt < 3) {
                #pragma unroll
                for (int j = 0; j < 2; j++) {
                    int f = tid + j * 256;
                    int ng = f & 31, k2 = f >> 5;
                    int kr = cch * 128 + (kt + 1) * 32 + k2 * 2;
                    rb0[j] = *(const float4*)(W2 + (size_t)kr * DDIM + ng * 4);
                    rb1[j] = *(const float4*)(W2 + (size_t)(kr + 1) * DDIM + ng * 4);
                }
            }
            const unsigned* Bb = Bs + cur * BBUF;
            #pragma unroll
            for (int ks = 0; ks < 2; ks++) {
                unsigned a[2][4];
                #pragma unroll
                for (int mt = 0; mt < 2; mt++) {
                    const unsigned* ap = Hs + (wm * 32 + mt * 16 + lg) * SY + (kt * 2 + ks) * 8 + lr;
                    a[mt][0] = ap[0];
                    a[mt][1] = ap[8 * SY];
                    a[mt][2] = ap[4];
                    a[mt][3] = ap[8 * SY + 4];
                }
                #pragma unroll
                for (int nt = 0; nt < 8; nt++) {
                    const unsigned* bp = Bb + (ks * 8 + lr) * SB + wn * 64 + nt * 8 + lg;
                    unsigned b0 = bp[0];
                    unsigned b1v = bp[4 * SB];
                    MMA_F16(acc2[0][nt], a[0], b0, b1v);
                    MMA_F16(acc2[1][nt], a[1], b0, b1v);
                }
            }
            if (kt < 3) {
                unsigned* Bd = Bs + (cur ^ 1) * BBUF;
                #pragma unroll
                for (int j = 0; j < 2; j++) {
                    int f = tid + j * 256;
                    int ng = f & 31, k2 = f >> 5;
                    uint4 u;
                    u.x = fh2(rb0[j].x, rb1[j].x); u.y = fh2(rb0[j].y, rb1[j].y);
                    u.z = fh2(rb0[j].z, rb1[j].z); u.w = fh2(rb0[j].w, rb1[j].w);
                    *(uint4*)(Bd + k2 * SB + ng * 4) = u;
                }
            }
            __syncthreads();
        }
    }

    // epilogue: + b2 + res
    #pragma unroll
    for (int mt = 0; mt < 2; mt++) {
        #pragma unroll
        for (int nt = 0; nt < 8; nt++) {
            int r = row0 + wm * 32 + mt * 16 + lg;
            int c = wn * 64 + nt * 8 + lr * 2;
            float bb0 = b2[c], bb1 = b2[c + 1];
            if (r < n) {
                float2 rr = *(const float2*)(res + (size_t)r * DDIM + c);
                *(float2*)(C + (size_t)r * DDIM + c) =
                    make_float2(acc2[mt][nt][0] + bb0 + rr.x,
                                acc2[mt][nt][1] + bb1 + rr.y);
            }
            if (r + 8 < n) {
                float2 rr = *(const float2*)(res + (size_t)(r + 8) * DDIM + c);
                *(float2*)(C + (size_t)(r + 8) * DDIM + c) =
                    make_float2(acc2[mt][nt][2] + bb0 + rr.x,
                                acc2[mt][nt][3] + bb1 + rr.y);
            }
        }
    }
}

// ---------------- launch ----------------
extern "C" void kernel_launch(void* const* d_in, const int* in_sizes, int n_in,
                              void* d_out, int out_size) {
    const float* node_feature = (const float*)d_in[0];
    const float* dist_attn    = (const float*)d_in[1];
    const float* path_attn    = (const float*)d_in[2];
    const int*   src          = (const int*)d_in[3];
    const int*   dst          = (const int*)d_in[4];
    const float* ln1_g        = (const float*)d_in[5];
    const float* ln1_b        = (const float*)d_in[6];
    const float* qkv_w        = (const float*)d_in[7];
    const float* qkv_b        = (const float*)d_in[8];
    const float* in_proj_w    = (const float*)d_in[9];
    const float* in_proj_b    = (const float*)d_in[10];
    const float* res_ln_g     = (const float*)d_in[11];
    const float* res_ln_b     = (const float*)d_in[12];
    const float* mlp_w1       = (const float*)d_in[13];
    const float* mlp_b1       = (const float*)d_in[14];
    const float* mlp_w2       = (const float*)d_in[15];
    const float* mlp_b2       = (const float*)d_in[16];
    float* out = (float*)d_out;

    cudaFuncSetAttribute(gemm_tc<0, 1>, cudaFuncAttributeMaxDynamicSharedMemorySize, GM_SMEM);
    cudaFuncSetAttribute(gemm_tc<1, 0>, cudaFuncAttributeMaxDynamicSharedMemorySize, GM_SMEM);
    cudaFuncSetAttribute(fmlp_kernel, cudaFuncAttributeMaxDynamicSharedMemorySize, FM_SMEM);

    void* p;
    cudaGetSymbolAddress(&p, g_h);    float*  ph   = (float*)p;
    cudaGetSymbolAddress(&p, g_hh);   __half* phh  = (__half*)p;
    cudaGetSymbolAddress(&p, g_qkv);  __half* pqkv = (__half*)p;
    cudaGetSymbolAddress(&p, g_agg);  float*  pagg = (float*)p;
    cudaGetSymbolAddress(&p, g_x);    float*  px   = (float*)p;
    cudaGetSymbolAddress(&p, g_yh);   __half* pyh  = (__half*)p;

    const int RB = (NN + 127) / 128;           // 391 row blocks
    const int LN_BLOCKS = (NN + 7) / 8;
    const int E_BLOCKS  = (EE + 255) / 256;
    const int N_BLOCKS  = (NN + 255) / 256;    // == NB
    const int ATTN_BLOCKS = (NN * 32 + 255) / 256;

    // CSR build
    zero_deg_kernel<<<N_BLOCKS, 256>>>();
    hist_kernel<<<E_BLOCKS, 256>>>(dst);
    scanA_kernel<<<NB, 256>>>();
    scanBC_kernel<<<NB, 256>>>();
    scatter_kernel<<<E_BLOCKS, 256>>>(dst);

    // main pipeline
    ln_kernel<<<LN_BLOCKS, 256>>>(node_feature, ln1_g, ln1_b, ph, phh, NN);
    gemm_tc<0, 1><<<dim3(3, RB), 256, GM_SMEM>>>(phh, qkv_w, qkv_b, nullptr, pqkv, NN, 384, 128);
    attn_kernel<<<ATTN_BLOCKS, 256>>>(src, dist_attn, path_attn);
    gemm_tc<1, 0><<<dim3(1, RB), 256, GM_SMEM>>>(pagg, in_proj_w, in_proj_b, ph, px, NN, 128, 128);
    ln_kernel<<<LN_BLOCKS, 256>>>(px, res_ln_g, res_ln_b, nullptr, pyh, NN);
    fmlp_kernel<<<RB, 256, FM_SMEM>>>(pyh, mlp_w1, mlp_b1, mlp_w2, mlp_b2, px, out, NN);
}

// round 12
// speedup vs baseline: 3.0432x; 1.0364x over previous
#include <cuda_runtime.h>
#include <cuda_fp16.h>
#include <math.h>

#define NN 50000
#define EE 600000
#define DDIM 128
#define HH 8
#define NB 196   // ceil(NN/256) scan blocks

// ---------------- scratch (static device memory; no allocs) ----------------
static __device__ float  g_h[NN * DDIM];           // LN1 output (float, residual)
static __device__ __half g_hh[NN * DDIM];          // LN1 output (half, GEMM A)
static __device__ __half g_qkv[NN * 3 * DDIM];     // [N][3][H][16] half
static __device__ float  g_agg[NN * DDIM];         // aggregated msgs (float)
static __device__ float  g_x[NN * DDIM];           // residual stream
static __device__ __half g_yh[NN * DDIM];          // LN2 output (half)
static __device__ int    g_deg[NN];
static __device__ int    g_off[NN + 1];
static __device__ int    g_pos[NN];
static __device__ int    g_esrc[EE];               // src node per CSR slot
static __device__ float  g_edp[EE * HH];           // dist+path per CSR slot
static __device__ int    g_bsum[NB];

// ---------------- CSR build ----------------
__global__ void zero_deg_kernel() {
    int i = blockIdx.x * blockDim.x + threadIdx.x;
    if (i < NN) g_deg[i] = 0;
}
__global__ void hist_kernel(const int* __restrict__ dst) {
    int e = blockIdx.x * blockDim.x + threadIdx.x;
    if (e < EE) atomicAdd(&g_deg[dst[e]], 1);
}
__global__ void scanA_kernel() {
    __shared__ int sh[256];
    int t = threadIdx.x;
    int i = blockIdx.x * 256 + t;
    int val = (i < NN) ? g_deg[i] : 0;
    sh[t] = val;
    #pragma unroll
    for (int o = 1; o < 256; o <<= 1) {
        __syncthreads();
        int x = (t >= o) ? sh[t - o] : 0;
        __syncthreads();
        sh[t] += x;
    }
    __syncthreads();
    int excl = sh[t] - val;
    if (i < NN) g_off[i] = excl;
    if (t == 255) g_bsum[blockIdx.x] = sh[255];
}
// merged scanB+scanC: each block reduces its own prefix of g_bsum
__global__ void scanBC_kernel() {
    __shared__ int sh[256];
    int t = threadIdx.x;
    sh[t] = (t < blockIdx.x && t < NB) ? g_bsum[t] : 0;
    __syncthreads();
    #pragma unroll
    for (int o = 128; o > 0; o >>= 1) {
        if (t < o) sh[t] += sh[t + o];
        __syncthreads();
    }
    int base = sh[0];
    int i = blockIdx.x * 256 + t;
    if (i < NN) {
        int v = g_off[i] + base;
        g_off[i] = v;
        g_pos[i] = v;
    }
    if (i == 0) g_off[NN] = EE;
}
// scatter + precompute: src node and (dist+path) land at CSR position, so
// attn reads them with NO gather chain (esrc direct, edp streaming).
__global__ void scatter_kernel(const int* __restrict__ src,
                               const int* __restrict__ dst,
                               const float* __restrict__ dist,
                               const float* __restrict__ path) {
    int e = blockIdx.x * blockDim.x + threadIdx.x;
    if (e >= EE) return;
    int d = dst[e];
    int p = atomicAdd(&g_pos[d], 1);
    g_esrc[p] = src[e];
    float4 d0 = *(const float4*)(dist + (size_t)e * 8);
    float4 d1 = *(const float4*)(dist + (size_t)e * 8 + 4);
    float4 p0 = *(const float4*)(path + (size_t)e * 8);
    float4 p1 = *(const float4*)(path + (size_t)e * 8 + 4);
    *(float4*)(g_edp + (size_t)p * 8) =
        make_float4(d0.x + p0.x, d0.y + p0.y, d0.z + p0.z, d0.w + p0.w);
    *(float4*)(g_edp + (size_t)p * 8 + 4) =
        make_float4(d1.x + p1.x, d1.y + p1.y, d1.z + p1.z, d1.w + p1.w);
}

// ---------------- fused attention: one warp per destination node ----------------
static __device__ __forceinline__ float4 ldqkv_h4(const __half* p) {
    uint2 u = *(const uint2*)p;
    float2 a = __half22float2(*reinterpret_cast<__half2*>(&u.x));
    float2 b = __half22float2(*reinterpret_cast<__half2*>(&u.y));
    return make_float4(a.x, a.y, b.x, b.y);
}

#define ALOAD(s, idx) do {                                                  \
    int s_ = g_esrc[idx];                                                   \
    q##s = ldqkv_h4(g_qkv + (size_t)s_ * 384 + lane * 4);                   \
    v##s = ldqkv_h4(g_qkv + (size_t)s_ * 384 + 256 + lane * 4);             \
    dp##s = g_edp[(size_t)(idx) * 8 + h];                                   \
} while (0)

#define ASTEP(s) do {                                                       \
    float dot = q##s.x * kv.x + q##s.y * kv.y + q##s.z * kv.z + q##s.w * kv.w; \
    dot += __shfl_xor_sync(0xFFFFFFFFu, dot, 1);                            \
    dot += __shfl_xor_sync(0xFFFFFFFFu, dot, 2);                            \
    float a_ = dot + dp##s;                                                 \
    float mn_ = fmaxf(m, a_);                                               \
    float corr_ = __expf(m - mn_);                                          \
    float p_ = __expf(a_ - mn_);                                            \
    den = den * corr_ + p_;                                                 \
    acc.x = acc.x * corr_ + v##s.x * p_;                                    \
    acc.y = acc.y * corr_ + v##s.y * p_;                                    \
    acc.z = acc.z * corr_ + v##s.z * p_;                                    \
    acc.w = acc.w * corr_ + v##s.w * p_;                                    \
    m = mn_;                                                                \
} while (0)

__global__ void attn_kernel() {
    int w = (blockIdx.x * blockDim.x + threadIdx.x) >> 5;
    if (w >= NN) return;
    int lane = threadIdx.x & 31;
    int h = lane >> 2;  // 4 lanes per head, 16 dims/head
    int beg = g_off[w], end = g_off[w + 1];
    float4 kv = ldqkv_h4(g_qkv + (size_t)w * 384 + 128 + lane * 4);
    float4 acc = make_float4(0.f, 0.f, 0.f, 0.f);
    float m = -1e30f, den = 0.f;
    int cnt = end - beg;

    if (cnt > 0) {
        float4 q0, v0, q1, v1, q2, v2, q3, v3;
        float dp0 = 0.f, dp1 = 0.f, dp2 = 0.f, dp3 = 0.f;
        ALOAD(0, beg);
        if (cnt > 1) ALOAD(1, beg + 1);
        if (cnt > 2) ALOAD(2, beg + 2);
        if (cnt > 3) ALOAD(3, beg + 3);
        int i = 0;
        while (i + 4 <= cnt) {
            ASTEP(0);
            if (i + 4 < cnt) ALOAD(0, beg + i + 4);
            ASTEP(1);
            if (i + 5 < cnt) ALOAD(1, beg + i + 5);
            ASTEP(2);
            if (i + 6 < cnt) ALOAD(2, beg + i + 6);
            ASTEP(3);
            if (i + 7 < cnt) ALOAD(3, beg + i + 7);
            i += 4;
        }
        int rem = cnt - i;   // 0..3; slots 0..rem-1 hold the tail
        if (rem > 0) ASTEP(0);
        if (rem > 1) ASTEP(1);
        if (rem > 2) ASTEP(2);
    }
    float inv = (den > 0.f) ? (1.0f / den) : 0.f;
    acc.x *= inv; acc.y *= inv; acc.z *= inv; acc.w *= inv;
    *(float4*)(g_agg + (size_t)w * DDIM + lane * 4) = acc;
}

// ---------------- half pack helper ----------------
static __device__ __forceinline__ unsigned fh2(float lo, float hi) {
    __half2 hv = __floats2half2_rn(lo, hi);
    return *reinterpret_cast<unsigned*>(&hv);
}

// ---------------- LayerNorm: one warp per row; dual float/half output ----------
__global__ void ln_kernel(const float* __restrict__ in,
                          const float* __restrict__ g,
                          const float* __restrict__ b,
                          float* __restrict__ outf,
                          __half* __restrict__ outh, int n) {
    int wid  = (blockIdx.x * blockDim.x + threadIdx.x) >> 5;
    int lane = threadIdx.x & 31;
    if (wid >= n) return;
    const float4* row = (const float4*)(in + (size_t)wid * DDIM);
    float4 x = row[lane];
    float s  = x.x + x.y + x.z + x.w;
    float s2 = x.x * x.x + x.y * x.y + x.z * x.z + x.w * x.w;
    #pragma unroll
    for (int o = 16; o > 0; o >>= 1) {
        s  += __shfl_xor_sync(0xFFFFFFFFu, s,  o);
        s2 += __shfl_xor_sync(0xFFFFFFFFu, s2, o);
    }
    float mu  = s  * (1.0f / 128.0f);
    float var = s2 * (1.0f / 128.0f) - mu * mu;
    float r   = rsqrtf(var + 1e-5f);
    float4 gg = ((const float4*)g)[lane];
    float4 bb = ((const float4*)b)[lane];
    float4 o4;
    o4.x = (x.x - mu) * r * gg.x + bb.x;
    o4.y = (x.y - mu) * r * gg.y + bb.y;
    o4.z = (x.z - mu) * r * gg.z + bb.z;
    o4.w = (x.w - mu) * r * gg.w + bb.w;
    if (outf)
        ((float4*)(outf + (size_t)wid * DDIM))[lane] = o4;
    if (outh)
        *(uint2*)(outh + (size_t)wid * DDIM + lane * 4) =
            make_uint2(fh2(o4.x, o4.y), fh2(o4.z, o4.w));
}

// ---------------- FP16 tensor-core GEMM (m16n8k16, fp32 accum) ----------------
#define SA 20
#define SB 136
#define ABUF (128 * SA)   // 2560 u32
#define BBUF (16 * SB)    // 2176 u32
#define GM_SMEM ((2 * ABUF + 2 * BBUF) * 4)  // 37888 B

#define MMA_F16(d, a, b0, b1)                                               \
    asm volatile("mma.sync.aligned.m16n8k16.row.col.f32.f16.f16.f32 "       \
                 "{%0,%1,%2,%3}, {%4,%5,%6,%7}, {%8,%9}, {%0,%1,%2,%3};"    \
                 : "+f"(d[0]), "+f"(d[1]), "+f"(d[2]), "+f"(d[3])           \
                 : "r"(a[0]), "r"(a[1]), "r"(a[2]), "r"(a[3]),              \
                   "r"(b0), "r"(b1))

static __device__ __forceinline__ float gelu_f(float v) {
    float t = tanhf(0.7978845608028654f * (v + 0.044715f * v * v * v));
    return 0.5f * v * (1.0f + t);
}

template <int EPI, int AHALF>
__global__ __launch_bounds__(256)
void gemm_tc(const void* __restrict__ Av,
             const float* __restrict__ W,
             const float* __restrict__ bias,
             const float* __restrict__ res,
             void* __restrict__ Cv,
             int n, int M, int K) {
    extern __shared__ unsigned sm[];
    unsigned* As = sm;                  // 2 x ABUF
    unsigned* Bs = sm + 2 * ABUF;       // 2 x BBUF

    const int tid  = threadIdx.x;
    const int lane = tid & 31, warp = tid >> 5;
    const int lg = lane >> 2, lr = lane & 3;
    const int wm = warp & 3,  wn = warp >> 2;
    const int row0 = blockIdx.y * 128;
    const int col0 = blockIdx.x * 128;
    const int KT = K >> 5;

    float acc[2][8][4];
    #pragma unroll
    for (int mt = 0; mt < 2; mt++)
        #pragma unroll
        for (int nt = 0; nt < 8; nt++)
            #pragma unroll
            for (int i = 0; i < 4; i++) acc[mt][nt][i] = 0.f;

    float4 raf[4];
    uint2  rah[4];
    float4 rb0[2], rb1[2];

    // -------- prologue: load + store tile 0 --------
    #pragma unroll
    for (int j = 0; j < 4; j++) {
        int f = tid + j * 256;
        int r = f >> 3, kc = f & 7;
        if (AHALF) {
            const __half* A = (const __half*)Av;
            uint2 v = make_uint2(0u, 0u);
            if (row0 + r < n)
                v = *(const uint2*)(A + (size_t)(row0 + r) * K + kc * 4);
            rah[j] = v;
        } else {
            const float* A = (const float*)Av;
            float4 v = make_float4(0.f, 0.f, 0.f, 0.f);
            if (row0 + r < n)
                v = *(const float4*)(A + (size_t)(row0 + r) * K + kc * 4);
            raf[j] = v;
        }
    }
    #pragma unroll
    for (int j = 0; j < 2; j++) {
        int f = tid + j * 256;
        int ng = f & 31, k2 = f >> 5;
        rb0[j] = *(const float4*)(W + (size_t)(k2 * 2) * M + col0 + ng * 4);
        rb1[j] = *(const float4*)(W + (size_t)(k2 * 2 + 1) * M + col0 + ng * 4);
    }
    #pragma unroll
    for (int j = 0; j < 4; j++) {
        int f = tid + j * 256;
        int r = f >> 3, kc = f & 7;
        if (AHALF)
            *(uint2*)(As + r * SA + kc * 2) = rah[j];
        else
            *(uint2*)(As + r * SA + kc * 2) =
                make_uint2(fh2(raf[j].x, raf[j].y), fh2(raf[j].z, raf[j].w));
    }
    #pragma unroll
    for (int j = 0; j < 2; j++) {
        int f = tid + j * 256;
        int ng = f & 31, k2 = f >> 5;
        uint4 u;
        u.x = fh2(rb0[j].x, rb1[j].x);
        u.y = fh2(rb0[j].y, rb1[j].y);
        u.z = fh2(rb0[j].z, rb1[j].z);
        u.w = fh2(rb0[j].w, rb1[j].w);
        *(uint4*)(Bs + k2 * SB + ng * 4) = u;
    }
    __syncthreads();

    for (int kt = 0; kt < KT; kt++) {
        const int cur = kt & 1;
        if (kt + 1 < KT) {
            #pragma unroll
            for (int j = 0; j < 4; j++) {
                int f = tid + j * 256;
                int r = f >> 3, kc = f & 7;
                if (AHALF) {
                    const __half* A = (const __half*)Av;
                    uint2 v = make_uint2(0u, 0u);
                    if (row0 + r < n)
                        v = *(const uint2*)(A + (size_t)(row0 + r) * K + (kt + 1) * 32 + kc * 4);
                    rah[j] = v;
                } else {
                    const float* A = (const float*)Av;
                    float4 v = make_float4(0.f, 0.f, 0.f, 0.f);
                    if (row0 + r < n)
                        v = *(const float4*)(A + (size_t)(row0 + r) * K + (kt + 1) * 32 + kc * 4);
                    raf[j] = v;
                }
            }
            #pragma unroll
            for (int j = 0; j < 2; j++) {
                int f = tid + j * 256;
                int ng = f & 31, k2 = f >> 5;
                int kr = (kt + 1) * 32 + k2 * 2;
                rb0[j] = *(const float4*)(W + (size_t)kr * M + col0 + ng * 4);
                rb1[j] = *(const float4*)(W + (size_t)(kr + 1) * M + col0 + ng * 4);
            }
        }
        const unsigned* Ab = As + cur * ABUF;
        const unsigned* Bb = Bs + cur * BBUF;
        #pragma unroll
        for (int ks = 0; ks < 2; ks++) {
            unsigned a[2][4];
            #pragma unroll
            for (int mt = 0; mt < 2; mt++) {
                const unsigned* ap = Ab + (wm * 32 + mt * 16 + lg) * SA + ks * 8 + lr;
                a[mt][0] = ap[0];
                a[mt][1] = ap[8 * SA];
                a[mt][2] = ap[4];
                a[mt][3] = ap[8 * SA + 4];
            }
            #pragma unroll
            for (int nt = 0; nt < 8; nt++) {
                const unsigned* bp = Bb + (ks * 8 + lr) * SB + wn * 64 + nt * 8 + lg;
                unsigned b0 = bp[0];
                unsigned b1 = bp[4 * SB];
                MMA_F16(acc[0][nt], a[0], b0, b1);
                MMA_F16(acc[1][nt], a[1], b0, b1);
            }
        }
        if (kt + 1 < KT) {
            unsigned* Ad = As + (cur ^ 1) * ABUF;
            unsigned* Bd = Bs + (cur ^ 1) * BBUF;
            #pragma unroll
            for (int j = 0; j < 4; j++) {
                int f = tid + j * 256;
                int r = f >> 3, kc = f & 7;
                if (AHALF)
                    *(uint2*)(Ad + r * SA + kc * 2) = rah[j];
                else
                    *(uint2*)(Ad + r * SA + kc * 2) =
                        make_uint2(fh2(raf[j].x, raf[j].y), fh2(raf[j].z, raf[j].w));
            }
            #pragma unroll
            for (int j = 0; j < 2; j++) {
                int f = tid + j * 256;
                int ng = f & 31, k2 = f >> 5;
                uint4 u;
                u.x = fh2(rb0[j].x, rb1[j].x);
                u.y = fh2(rb0[j].y, rb1[j].y);
                u.z = fh2(rb0[j].z, rb1[j].z);
                u.w = fh2(rb0[j].w, rb1[j].w);
                *(uint4*)(Bd + k2 * SB + ng * 4) = u;
            }
        }
        __syncthreads();
    }

    const float sc = 0.08838834764831845f;  // D^-0.5
    #pragma unroll
    for (int mt = 0; mt < 2; mt++) {
        #pragma unroll
        for (int nt = 0; nt < 8; nt++) {
            int r = row0 + wm * 32 + mt * 16 + lg;
            int c = col0 + wn * 64 + nt * 8 + lr * 2;
            float b0 = bias[c], b1 = bias[c + 1];
            float v0 = acc[mt][nt][0] + b0;
            float v1 = acc[mt][nt][1] + b1;
            float v2 = acc[mt][nt][2] + b0;
            float v3 = acc[mt][nt][3] + b1;
            if (EPI == 0) {
                if (blockIdx.x == 0) {  // q columns
                    v0 *= sc; v1 *= sc; v2 *= sc; v3 *= sc;
                }
                __half* C = (__half*)Cv;
                if (r < n)
                    *(__half2*)(C + (size_t)r * M + c) = __floats2half2_rn(v0, v1);
                if (r + 8 < n)
                    *(__half2*)(C + (size_t)(r + 8) * M + c) = __floats2half2_rn(v2, v3);
            } else {
                float* C = (float*)Cv;
                if (r < n) {
                    float2 rr = *(const float2*)(res + (size_t)r * M + c);
                    *(float2*)(C + (size_t)r * M + c) =
                        make_float2(v0 + rr.x, v1 + rr.y);
                }
                if (r + 8 < n) {
                    float2 rr = *(const float2*)(res + (size_t)(r + 8) * M + c);
                    *(float2*)(C + (size_t)(r + 8) * M + c) =
                        make_float2(v2 + rr.x, v3 + rr.y);
                }
            }
        }
    }
}

// ---------------- fused MLP (fp16 in): out = res + gelu(Y@W1+b1)@W2 + b2 -----
#define SY 68                 // u32 stride for 128-half rows
#define YBUF (128 * SY)
#define FM_SMEM ((2 * YBUF + 2 * BBUF) * 4)  // 87040 B

__global__ __launch_bounds__(256)
void fmlp_kernel(const __half* __restrict__ Y,
                 const float* __restrict__ W1,
                 const float* __restrict__ b1,
                 const float* __restrict__ W2,
                 const float* __restrict__ b2,
                 const float* __restrict__ res,
                 float* __restrict__ C, int n) {
    extern __shared__ unsigned sm[];
    unsigned* Ys = sm;                 // 128 x SY
    unsigned* Hs = sm + YBUF;          // 128 x SY
    unsigned* Bs = sm + 2 * YBUF;      // 2 x BBUF

    const int tid  = threadIdx.x;
    const int lane = tid & 31, warp = tid >> 5;
    const int lg = lane >> 2, lr = lane & 3;
    const int wm = warp & 3,  wn = warp >> 2;
    const int row0 = blockIdx.x * 128;

    // stage Y tile (128 x 128 halves) zero-conversion
    #pragma unroll
    for (int j = 0; j < 16; j++) {
        int f = tid + j * 256;
        int r = f >> 5, c4 = f & 31;
        uint2 v = make_uint2(0u, 0u);
        if (row0 + r < n)
            v = *(const uint2*)(Y + (size_t)(row0 + r) * DDIM + c4 * 4);
        *(uint2*)(Ys + r * SY + c4 * 2) = v;
    }

    float acc2[2][8][4];
    #pragma unroll
    for (int mt = 0; mt < 2; mt++)
        #pragma unroll
        for (int nt = 0; nt < 8; nt++)
            #pragma unroll
            for (int i = 0; i < 4; i++) acc2[mt][nt][i] = 0.f;

    float4 rb0[2], rb1[2];
    __syncthreads();

    for (int cch = 0; cch < 4; cch++) {
        // ---- phase 1: H = Y @ W1[:, cch*128 .. +128] ----
        float acc[2][8][4];
        #pragma unroll
        for (int mt = 0; mt < 2; mt++)
            #pragma unroll
            for (int nt = 0; nt < 8; nt++)
                #pragma unroll
                for (int i = 0; i < 4; i++) acc[mt][nt][i] = 0.f;

        #pragma unroll
        for (int j = 0; j < 2; j++) {
            int f = tid + j * 256;
            int ng = f & 31, k2 = f >> 5;
            float4 w0 = *(const float4*)(W1 + (size_t)(k2 * 2) * 512 + cch * 128 + ng * 4);
            float4 w1 = *(const float4*)(W1 + (size_t)(k2 * 2 + 1) * 512 + cch * 128 + ng * 4);
            uint4 u;
            u.x = fh2(w0.x, w1.x); u.y = fh2(w0.y, w1.y);
            u.z = fh2(w0.z, w1.z); u.w = fh2(w0.w, w1.w);
            *(uint4*)(Bs + k2 * SB + ng * 4) = u;
        }
        __syncthreads();

        #pragma unroll
        for (int kt = 0; kt < 4; kt++) {
            const int cur = kt & 1;
            if (kt < 3) {
                #pragma unroll
                for (int j = 0; j < 2; j++) {
                    int f = tid + j * 256;
                    int ng = f & 31, k2 = f >> 5;
                    int kr = (kt + 1) * 32 + k2 * 2;
                    rb0[j] = *(const float4*)(W1 + (size_t)kr * 512 + cch * 128 + ng * 4);
                    rb1[j] = *(const float4*)(W1 + (size_t)(kr + 1) * 512 + cch * 128 + ng * 4);
                }
            }
            const unsigned* Bb = Bs + cur * BBUF;
            #pragma unroll
            for (int ks = 0; ks < 2; ks++) {
                unsigned a[2][4];
                #pragma unroll
                for (int mt = 0; mt < 2; mt++) {
                    const unsigned* ap = Ys + (wm * 32 + mt * 16 + lg) * SY + (kt * 2 + ks) * 8 + lr;
                    a[mt][0] = ap[0];
                    a[mt][1] = ap[8 * SY];
                    a[mt][2] = ap[4];
                    a[mt][3] = ap[8 * SY + 4];
                }
                #pragma unroll
                for (int nt = 0; nt < 8; nt++) {
                    const unsigned* bp = Bb + (ks * 8 + lr) * SB + wn * 64 + nt * 8 + lg;
                    unsigned b0 = bp[0];
                    unsigned b1v = bp[4 * SB];
                    MMA_F16(acc[0][nt], a[0], b0, b1v);
                    MMA_F16(acc[1][nt], a[1], b0, b1v);
                }
            }
            if (kt < 3) {
                unsigned* Bd = Bs + (cur ^ 1) * BBUF;
                #pragma unroll
                for (int j = 0; j < 2; j++) {
                    int f = tid + j * 256;
                    int ng = f & 31, k2 = f >> 5;
                    uint4 u;
                    u.x = fh2(rb0[j].x, rb1[j].x); u.y = fh2(rb0[j].y, rb1[j].y);
                    u.z = fh2(rb0[j].z, rb1[j].z); u.w = fh2(rb0[j].w, rb1[j].w);
                    *(uint4*)(Bd + k2 * SB + ng * 4) = u;
                }
            }
            __syncthreads();
        }

        // gelu + b1 -> Hs (fp16)
        #pragma unroll
        for (int mt = 0; mt < 2; mt++) {
            #pragma unroll
            for (int nt = 0; nt < 8; nt++) {
                int rloc = wm * 32 + mt * 16 + lg;
                int cu = wn * 32 + nt * 4 + lr;   // u32 column index
                float bb0 = b1[cch * 128 + cu * 2];
                float bb1 = b1[cch * 128 + cu * 2 + 1];
                Hs[rloc * SY + cu] =
                    fh2(gelu_f(acc[mt][nt][0] + bb0), gelu_f(acc[mt][nt][1] + bb1));
                Hs[(rloc + 8) * SY + cu] =
                    fh2(gelu_f(acc[mt][nt][2] + bb0), gelu_f(acc[mt][nt][3] + bb1));
            }
        }
        __syncthreads();

        // ---- phase 2: acc2 += H @ W2[cch*128 .. +128, :] ----
        #pragma unroll
        for (int j = 0; j < 2; j++) {
            int f = tid + j * 256;
            int ng = f & 31, k2 = f >> 5;
            float4 w0 = *(const float4*)(W2 + (size_t)(cch * 128 + k2 * 2) * DDIM + ng * 4);
            float4 w1 = *(const float4*)(W2 + (size_t)(cch * 128 + k2 * 2 + 1) * DDIM + ng * 4);
            uint4 u;
            u.x = fh2(w0.x, w1.x); u.y = fh2(w0.y, w1.y);
            u.z = fh2(w0.z, w1.z); u.w = fh2(w0.w, w1.w);
            *(uint4*)(Bs + k2 * SB + ng * 4) = u;
        }
        __syncthreads();

        #pragma unroll
        for (int kt = 0; kt < 4; kt++) {
            const int cur = kt & 1;
            if (kt < 3) {
                #pragma unroll
                for (int j = 0; j < 2; j++) {
                    int f = tid + j * 256;
                    int ng = f & 31, k2 = f >> 5;
                    int kr = cch * 128 + (kt + 1) * 32 + k2 * 2;
                    rb0[j] = *(const float4*)(W2 + (size_t)kr * DDIM + ng * 4);
                    rb1[j] = *(const float4*)(W2 + (size_t)(kr + 1) * DDIM + ng * 4);
                }
            }
            const unsigned* Bb = Bs + cur * BBUF;
            #pragma unroll
            for (int ks = 0; ks < 2; ks++) {
                unsigned a[2][4];
                #pragma unroll
                for (int mt = 0; mt < 2; mt++) {
                    const unsigned* ap = Hs + (wm * 32 + mt * 16 + lg) * SY + (kt * 2 + ks) * 8 + lr;
                    a[mt][0] = ap[0];
                    a[mt][1] = ap[8 * SY];
                    a[mt][2] = ap[4];
                    a[mt][3] = ap[8 * SY + 4];
                }
                #pragma unroll
                for (int nt = 0; nt < 8; nt++) {
                    const unsigned* bp = Bb + (ks * 8 + lr) * SB + wn * 64 + nt * 8 + lg;
                    unsigned b0 = bp[0];
                    unsigned b1v = bp[4 * SB];
                    MMA_F16(acc2[0][nt], a[0], b0, b1v);
                    MMA_F16(acc2[1][nt], a[1], b0, b1v);
                }
            }
            if (kt < 3) {
                unsigned* Bd = Bs + (cur ^ 1) * BBUF;
                #pragma unroll
                for (int j = 0; j < 2; j++) {
                    int f = tid + j * 256;
                    int ng = f & 31, k2 = f >> 5;
                    uint4 u;
                    u.x = fh2(rb0[j].x, rb1[j].x); u.y = fh2(rb0[j].y, rb1[j].y);
                    u.z = fh2(rb0[j].z, rb1[j].z); u.w = fh2(rb0[j].w, rb1[j].w);
                    *(uint4*)(Bd + k2 * SB + ng * 4) = u;
                }
            }
            __syncthreads();
        }
    }

    // epilogue: + b2 + res
    #pragma unroll
    for (int mt = 0; mt < 2; mt++) {
        #pragma unroll
        for (int nt = 0; nt < 8; nt++) {
            int r = row0 + wm * 32 + mt * 16 + lg;
            int c = wn * 64 + nt * 8 + lr * 2;
            float bb0 = b2[c], bb1 = b2[c + 1];
            if (r < n) {
                float2 rr = *(const float2*)(res + (size_t)r * DDIM + c);
                *(float2*)(C + (size_t)r * DDIM + c) =
                    make_float2(acc2[mt][nt][0] + bb0 + rr.x,
                                acc2[mt][nt][1] + bb1 + rr.y);
            }
            if (r + 8 < n) {
                float2 rr = *(const float2*)(res + (size_t)(r + 8) * DDIM + c);
                *(float2*)(C + (size_t)(r + 8) * DDIM + c) =
                    make_float2(acc2[mt][nt][2] + bb0 + rr.x,
                                acc2[mt][nt][3] + bb1 + rr.y);
            }
        }
    }
}

// ---------------- launch ----------------
extern "C" void kernel_launch(void* const* d_in, const int* in_sizes, int n_in,
                              void* d_out, int out_size) {
    const float* node_feature = (const float*)d_in[0];
    const float* dist_attn    = (const float*)d_in[1];
    const float* path_attn    = (const float*)d_in[2];
    const int*   src          = (const int*)d_in[3];
    const int*   dst          = (const int*)d_in[4];
    const float* ln1_g        = (const float*)d_in[5];
    const float* ln1_b        = (const float*)d_in[6];
    const float* qkv_w        = (const float*)d_in[7];
    const float* qkv_b        = (const float*)d_in[8];
    const float* in_proj_w    = (const float*)d_in[9];
    const float* in_proj_b    = (const float*)d_in[10];
    const float* res_ln_g     = (const float*)d_in[11];
    const float* res_ln_b     = (const float*)d_in[12];
    const float* mlp_w1       = (const float*)d_in[13];
    const float* mlp_b1       = (const float*)d_in[14];
    const float* mlp_w2       = (const float*)d_in[15];
    const float* mlp_b2       = (const float*)d_in[16];
    float* out = (float*)d_out;

    cudaFuncSetAttribute(gemm_tc<0, 1>, cudaFuncAttributeMaxDynamicSharedMemorySize, GM_SMEM);
    cudaFuncSetAttribute(gemm_tc<1, 0>, cudaFuncAttributeMaxDynamicSharedMemorySize, GM_SMEM);
    cudaFuncSetAttribute(fmlp_kernel, cudaFuncAttributeMaxDynamicSharedMemorySize, FM_SMEM);

    void* p;
    cudaGetSymbolAddress(&p, g_h);    float*  ph   = (float*)p;
    cudaGetSymbolAddress(&p, g_hh);   __half* phh  = (__half*)p;
    cudaGetSymbolAddress(&p, g_qkv);  __half* pqkv = (__half*)p;
    cudaGetSymbolAddress(&p, g_agg);  float*  pagg = (float*)p;
    cudaGetSymbolAddress(&p, g_x);    float*  px   = (float*)p;
    cudaGetSymbolAddress(&p, g_yh);   __half* pyh  = (__half*)p;

    const int RB = (NN + 127) / 128;           // 391 row blocks
    const int LN_BLOCKS = (NN + 7) / 8;
    const int E_BLOCKS  = (EE + 255) / 256;
    const int N_BLOCKS  = (NN + 255) / 256;    // == NB
    const int ATTN_BLOCKS = (NN * 32 + 255) / 256;

    // CSR build (+ precompute of src & dist+path in CSR order)
    zero_deg_kernel<<<N_BLOCKS, 256>>>();
    hist_kernel<<<E_BLOCKS, 256>>>(dst);
    scanA_kernel<<<NB, 256>>>();
    scanBC_kernel<<<NB, 256>>>();
    scatter_kernel<<<E_BLOCKS, 256>>>(src, dst, dist_attn, path_attn);

    // main pipeline
    ln_kernel<<<LN_BLOCKS, 256>>>(node_feature, ln1_g, ln1_b, ph, phh, NN);
    gemm_tc<0, 1><<<dim3(3, RB), 256, GM_SMEM>>>(phh, qkv_w, qkv_b, nullptr, pqkv, NN, 384, 128);
    attn_kernel<<<ATTN_BLOCKS, 256>>>();
    gemm_tc<1, 0><<<dim3(1, RB), 256, GM_SMEM>>>(pagg, in_proj_w, in_proj_b, ph, px, NN, 128, 128);
    ln_kernel<<<LN_BLOCKS, 256>>>(px, res_ln_g, res_ln_b, nullptr, pyh, NN);
    fmlp_kernel<<<RB, 256, FM_SMEM>>>(pyh, mlp_w1, mlp_b1, mlp_w2, mlp_b2, px, out, NN);
}

// round 14
// speedup vs baseline: 3.2294x; 1.0612x over previous
#include <cuda_runtime.h>
#include <cuda_fp16.h>
#include <math.h>

#define NN 50000
#define EE 600000
#define DDIM 128
#define HH 8
#define NB 196   // ceil(NN/256) scan blocks
#define NBLK 196 // N_BLOCKS == NB

// ---------------- scratch (static device memory; no allocs) ----------------
static __device__ float  g_h[NN * DDIM];           // LN1 output (float, residual)
static __device__ __half g_hh[NN * DDIM];          // LN1 output (half, GEMM A)
static __device__ __half g_qkv[NN * 3 * DDIM];     // [N][3][H][16] half
static __device__ __half g_agg[NN * DDIM];         // aggregated msgs (half)
static __device__ float  g_x[NN * DDIM];           // residual stream
static __device__ __half g_yh[NN * DDIM];          // LN2 output (half)
static __device__ int    g_deg[NN];
static __device__ int    g_off[NN + 1];
static __device__ int    g_pos[NN];
static __device__ int    g_esrc[EE];               // src node per CSR slot
static __device__ float  g_edp[EE * HH];           // dist+path per CSR slot
static __device__ int    g_bsum[NB];

// ---------------- half pack/unpack helpers ----------------
static __device__ __forceinline__ unsigned fh2(float lo, float hi) {
    __half2 hv = __floats2half2_rn(lo, hi);
    return *reinterpret_cast<unsigned*>(&hv);
}
static __device__ __forceinline__ void ldh8(const __half* p, float* o) {
    uint4 u = *(const uint4*)p;
    __half2* hp = (__half2*)&u;
    #pragma unroll
    for (int j = 0; j < 4; j++) {
        float2 f = __half22float2(hp[j]);
        o[2 * j] = f.x; o[2 * j + 1] = f.y;
    }
}

// ---------------- CSR build ----------------
__global__ void hist_kernel(const int* __restrict__ dst) {
    int e = blockIdx.x * blockDim.x + threadIdx.x;
    if (e < EE) atomicAdd(&g_deg[dst[e]], 1);
}
__global__ void scanA_kernel() {
    __shared__ int sh[256];
    int t = threadIdx.x;
    int i = blockIdx.x * 256 + t;
    int val = (i < NN) ? g_deg[i] : 0;
    sh[t] = val;
    #pragma unroll
    for (int o = 1; o < 256; o <<= 1) {
        __syncthreads();
        int x = (t >= o) ? sh[t - o] : 0;
        __syncthreads();
        sh[t] += x;
    }
    __syncthreads();
    int excl = sh[t] - val;
    if (i < NN) g_off[i] = excl;
    if (t == 255) g_bsum[blockIdx.x] = sh[255];
}
// merged scanB+scanC: each block reduces its own prefix of g_bsum
__global__ void scanBC_kernel() {
    __shared__ int sh[256];
    int t = threadIdx.x;
    sh[t] = (t < blockIdx.x && t < NB) ? g_bsum[t] : 0;
    __syncthreads();
    #pragma unroll
    for (int o = 128; o > 0; o >>= 1) {
        if (t < o) sh[t] += sh[t + o];
        __syncthreads();
    }
    int base = sh[0];
    int i = blockIdx.x * 256 + t;
    if (i < NN) {
        int v = g_off[i] + base;
        g_off[i] = v;
        g_pos[i] = v;
    }
    if (i == 0) g_off[NN] = EE;
}
// scatter + precompute: src node and (dist+path) land at CSR position.
__global__ void scatter_kernel(const int* __restrict__ src,
                               const int* __restrict__ dst,
                               const float* __restrict__ dist,
                               const float* __restrict__ path) {
    int e = blockIdx.x * blockDim.x + threadIdx.x;
    if (e >= EE) return;
    int d = dst[e];
    int p = atomicAdd(&g_pos[d], 1);
    g_esrc[p] = src[e];
    float4 d0 = *(const float4*)(dist + (size_t)e * 8);
    float4 d1 = *(const float4*)(dist + (size_t)e * 8 + 4);
    float4 p0 = *(const float4*)(path + (size_t)e * 8);
    float4 p1 = *(const float4*)(path + (size_t)e * 8 + 4);
    *(float4*)(g_edp + (size_t)p * 8) =
        make_float4(d0.x + p0.x, d0.y + p0.y, d0.z + p0.z, d0.w + p0.w);
    *(float4*)(g_edp + (size_t)p * 8 + 4) =
        make_float4(d1.x + p1.x, d1.y + p1.y, d1.z + p1.z, d1.w + p1.w);
}

// ---------------- merged zero_deg + LN1 ----------------
__global__ void zero_ln_kernel(const float* __restrict__ in,
                               const float* __restrict__ g,
                               const float* __restrict__ b,
                               float* __restrict__ outf,
                               __half* __restrict__ outh) {
    if (blockIdx.x < NBLK) {
        int i = blockIdx.x * 256 + threadIdx.x;
        if (i < NN) g_deg[i] = 0;
        return;
    }
    int wid  = ((blockIdx.x - NBLK) * 256 + threadIdx.x) >> 5;
    int lane = threadIdx.x & 31;
    if (wid >= NN) return;
    const float4* row = (const float4*)(in + (size_t)wid * DDIM);
    float4 x = row[lane];
    float s  = x.x + x.y + x.z + x.w;
    float s2 = x.x * x.x + x.y * x.y + x.z * x.z + x.w * x.w;
    #pragma unroll
    for (int o = 16; o > 0; o >>= 1) {
        s  += __shfl_xor_sync(0xFFFFFFFFu, s,  o);
        s2 += __shfl_xor_sync(0xFFFFFFFFu, s2, o);
    }
    float mu  = s  * (1.0f / 128.0f);
    float var = s2 * (1.0f / 128.0f) - mu * mu;
    float r   = rsqrtf(var + 1e-5f);
    float4 gg = ((const float4*)g)[lane];
    float4 bb = ((const float4*)b)[lane];
    float4 o4;
    o4.x = (x.x - mu) * r * gg.x + bb.x;
    o4.y = (x.y - mu) * r * gg.y + bb.y;
    o4.z = (x.z - mu) * r * gg.z + bb.z;
    o4.w = (x.w - mu) * r * gg.w + bb.w;
    ((float4*)(outf + (size_t)wid * DDIM))[lane] = o4;
    *(uint2*)(outh + (size_t)wid * DDIM + lane * 4) =
        make_uint2(fh2(o4.x, o4.y), fh2(o4.z, o4.w));
}

// ---------------- LayerNorm (ln2): half-only output ----------------
__global__ void ln_kernel(const float* __restrict__ in,
                          const float* __restrict__ g,
                          const float* __restrict__ b,
                          __half* __restrict__ outh, int n) {
    int wid  = (blockIdx.x * blockDim.x + threadIdx.x) >> 5;
    int lane = threadIdx.x & 31;
    if (wid >= n) return;
    const float4* row = (const float4*)(in + (size_t)wid * DDIM);
    float4 x = row[lane];
    float s  = x.x + x.y + x.z + x.w;
    float s2 = x.x * x.x + x.y * x.y + x.z * x.z + x.w * x.w;
    #pragma unroll
    for (int o = 16; o > 0; o >>= 1) {
        s  += __shfl_xor_sync(0xFFFFFFFFu, s,  o);
        s2 += __shfl_xor_sync(0xFFFFFFFFu, s2, o);
    }
    float mu  = s  * (1.0f / 128.0f);
    float var = s2 * (1.0f / 128.0f) - mu * mu;
    float r   = rsqrtf(var + 1e-5f);
    float4 gg = ((const float4*)g)[lane];
    float4 bb = ((const float4*)b)[lane];
    float4 o4;
    o4.x = (x.x - mu) * r * gg.x + bb.x;
    o4.y = (x.y - mu) * r * gg.y + bb.y;
    o4.z = (x.z - mu) * r * gg.z + bb.z;
    o4.w = (x.w - mu) * r * gg.w + bb.w;
    *(uint2*)(outh + (size_t)wid * DDIM + lane * 4) =
        make_uint2(fh2(o4.x, o4.y), fh2(o4.z, o4.w));
}

// ---------------- fused attention: warp = dst, 2 edges in flight -------------
// Lanes 0-15 process even CSR slots, lanes 16-31 odd slots. Each lane covers
// 8 dims (head = l16/2). BOTH halves run steps = ceil(cnt/2) iterations
// (warp-uniform): the odd half's phantom edge gets dp = -1e38 so its softmax
// weight is exactly 0. All shfl_syncs execute fully converged.
#define ALOAD2(s, i) do {                                                   \
    int off_ = gho + ((i) << 1);                                            \
    int idx_ = beg + (off_ < cnt ? off_ : cnt - 1);                         \
    int s_ = g_esrc[idx_];                                                  \
    ldh8(g_qkv + (size_t)s_ * 384 + l16 * 8, q##s);                         \
    ldh8(g_qkv + (size_t)s_ * 384 + 256 + l16 * 8, v##s);                   \
    dp##s = (off_ < cnt) ? g_edp[(size_t)idx_ * 8 + h2] : -1e38f;           \
} while (0)

#define ASTEP2(s) do {                                                      \
    float p_ = q##s[0] * kv[0] + q##s[1] * kv[1] + q##s[2] * kv[2]          \
             + q##s[3] * kv[3] + q##s[4] * kv[4] + q##s[5] * kv[5]          \
             + q##s[6] * kv[6] + q##s[7] * kv[7];                           \
    float dot_ = p_ + __shfl_xor_sync(0xFFFFFFFFu, p_, 1);                  \
    float a_ = dot_ + dp##s;                                                \
    float mn_ = fmaxf(m, a_);                                               \
    float corr_ = __expf(m - mn_);                                          \
    float pw_ = __expf(a_ - mn_);                                           \
    den = den * corr_ + pw_;                                                \
    _Pragma("unroll")                                                       \
    for (int j_ = 0; j_ < 8; j_++)                                          \
        acc[j_] = acc[j_] * corr_ + v##s[j_] * pw_;                         \
    m = mn_;                                                                \
} while (0)

__global__ void attn_kernel() {
    int w = (blockIdx.x * blockDim.x + threadIdx.x) >> 5;
    if (w >= NN) return;
    int lane = threadIdx.x & 31;
    int gho = lane >> 4;     // half-warp id (edge parity)
    int l16 = lane & 15;     // lane within half: dims [l16*8, l16*8+8)
    int h2  = l16 >> 1;      // head
    int beg = g_off[w], end = g_off[w + 1];
    int cnt = end - beg;     // warp-uniform
    float kv[8];
    ldh8(g_qkv + (size_t)w * 384 + 128 + l16 * 8, kv);
    float acc[8];
    #pragma unroll
    for (int j = 0; j < 8; j++) acc[j] = 0.f;
    float m = -1e30f, den = 0.f;

    int steps = (cnt + 1) >> 1;   // warp-uniform iteration count
    if (steps > 0) {
        float q0[8], v0[8], q1[8], v1[8];
        float dp0 = 0.f, dp1 = 0.f;
        ALOAD2(0, 0);
        if (steps > 1) ALOAD2(1, 1);
        int i = 0;
        while (i + 2 <= steps) {
            ASTEP2(0);
            if (i + 2 < steps) ALOAD2(0, i + 2);
            ASTEP2(1);
            if (i + 3 < steps) ALOAD2(1, i + 3);
            i += 2;
        }
        if (i < steps) ASTEP2(0);
    }

    // merge the two half-warp softmax states (exact)
    float mo  = __shfl_xor_sync(0xFFFFFFFFu, m, 16);
    float dno = __shfl_xor_sync(0xFFFFFFFFu, den, 16);
    float mn  = fmaxf(m, mo);
    float cs  = __expf(m - mn);
    float co  = __expf(mo - mn);
    float dtot = den * cs + dno * co;
    #pragma unroll
    for (int j = 0; j < 8; j++) {
        float ao = __shfl_xor_sync(0xFFFFFFFFu, acc[j], 16);
        acc[j] = acc[j] * cs + ao * co;
    }
    float inv = (dtot > 0.f) ? (1.0f / dtot) : 0.f;
    if (gho == 0) {
        uint4 o;
        o.x = fh2(acc[0] * inv, acc[1] * inv);
        o.y = fh2(acc[2] * inv, acc[3] * inv);
        o.z = fh2(acc[4] * inv, acc[5] * inv);
        o.w = fh2(acc[6] * inv, acc[7] * inv);
        *(uint4*)(g_agg + (size_t)w * DDIM + l16 * 8) = o;
    }
}

// ---------------- FP16 tensor-core GEMM (m16n8k16, fp32 accum) ----------------
#define SA 20
#define SB 136
#define ABUF (128 * SA)   // 2560 u32
#define BBUF (16 * SB)    // 2176 u32
#define GM_SMEM ((2 * ABUF + 2 * BBUF) * 4)  // 37888 B

#define MMA_F16(d, a, b0, b1)                                               \
    asm volatile("mma.sync.aligned.m16n8k16.row.col.f32.f16.f16.f32 "       \
                 "{%0,%1,%2,%3}, {%4,%5,%6,%7}, {%8,%9}, {%0,%1,%2,%3};"    \
                 : "+f"(d[0]), "+f"(d[1]), "+f"(d[2]), "+f"(d[3])           \
                 : "r"(a[0]), "r"(a[1]), "r"(a[2]), "r"(a[3]),              \
                   "r"(b0), "r"(b1))

static __device__ __forceinline__ float gelu_f(float v) {
    float t = tanhf(0.7978845608028654f * (v + 0.044715f * v * v * v));
    return 0.5f * v * (1.0f + t);
}

template <int EPI>
__global__ __launch_bounds__(256)
void gemm_tc(const __half* __restrict__ A,
             const float* __restrict__ W,
             const float* __restrict__ bias,
             const float* __restrict__ res,
             void* __restrict__ Cv,
             int n, int M, int K) {
    extern __shared__ unsigned sm[];
    unsigned* As = sm;                  // 2 x ABUF
    unsigned* Bs = sm + 2 * ABUF;       // 2 x BBUF

    const int tid  = threadIdx.x;
    const int lane = tid & 31, warp = tid >> 5;
    const int lg = lane >> 2, lr = lane & 3;
    const int wm = warp & 3,  wn = warp >> 2;
    const int row0 = blockIdx.y * 128;
    const int col0 = blockIdx.x * 128;
    const int KT = K >> 5;

    float acc[2][8][4];
    #pragma unroll
    for (int mt = 0; mt < 2; mt++)
        #pragma unroll
        for (int nt = 0; nt < 8; nt++)
            #pragma unroll
            for (int i = 0; i < 4; i++) acc[mt][nt][i] = 0.f;

    uint2  rah[4];
    float4 rb0[2], rb1[2];

    // -------- prologue: load + store tile 0 --------
    #pragma unroll
    for (int j = 0; j < 4; j++) {
        int f = tid + j * 256;
        int r = f >> 3, kc = f & 7;
        uint2 v = make_uint2(0u, 0u);
        if (row0 + r < n)
            v = *(const uint2*)(A + (size_t)(row0 + r) * K + kc * 4);
        rah[j] = v;
    }
    #pragma unroll
    for (int j = 0; j < 2; j++) {
        int f = tid + j * 256;
        int ng = f & 31, k2 = f >> 5;
        rb0[j] = *(const float4*)(W + (size_t)(k2 * 2) * M + col0 + ng * 4);
        rb1[j] = *(const float4*)(W + (size_t)(k2 * 2 + 1) * M + col0 + ng * 4);
    }
    #pragma unroll
    for (int j = 0; j < 4; j++) {
        int f = tid + j * 256;
        int r = f >> 3, kc = f & 7;
        *(uint2*)(As + r * SA + kc * 2) = rah[j];
    }
    #pragma unroll
    for (int j = 0; j < 2; j++) {
        int f = tid + j * 256;
        int ng = f & 31, k2 = f >> 5;
        uint4 u;
        u.x = fh2(rb0[j].x, rb1[j].x);
        u.y = fh2(rb0[j].y, rb1[j].y);
        u.z = fh2(rb0[j].z, rb1[j].z);
        u.w = fh2(rb0[j].w, rb1[j].w);
        *(uint4*)(Bs + k2 * SB + ng * 4) = u;
    }
    __syncthreads();

    for (int kt = 0; kt < KT; kt++) {
        const int cur = kt & 1;
        if (kt + 1 < KT) {
            #pragma unroll
            for (int j = 0; j < 4; j++) {
                int f = tid + j * 256;
                int r = f >> 3, kc = f & 7;
                uint2 v = make_uint2(0u, 0u);
                if (row0 + r < n)
                    v = *(const uint2*)(A + (size_t)(row0 + r) * K + (kt + 1) * 32 + kc * 4);
                rah[j] = v;
            }
            #pragma unroll
            for (int j = 0; j < 2; j++) {
                int f = tid + j * 256;
                int ng = f & 31, k2 = f >> 5;
                int kr = (kt + 1) * 32 + k2 * 2;
                rb0[j] = *(const float4*)(W + (size_t)kr * M + col0 + ng * 4);
                rb1[j] = *(const float4*)(W + (size_t)(kr + 1) * M + col0 + ng * 4);
            }
        }
        const unsigned* Ab = As + cur * ABUF;
        const unsigned* Bb = Bs + cur * BBUF;
        #pragma unroll
        for (int ks = 0; ks < 2; ks++) {
            unsigned a[2][4];
            #pragma unroll
            for (int mt = 0; mt < 2; mt++) {
                const unsigned* ap = Ab + (wm * 32 + mt * 16 + lg) * SA + ks * 8 + lr;
                a[mt][0] = ap[0];
                a[mt][1] = ap[8 * SA];
                a[mt][2] = ap[4];
                a[mt][3] = ap[8 * SA + 4];
            }
            #pragma unroll
            for (int nt = 0; nt < 8; nt++) {
                const unsigned* bp = Bb + (ks * 8 + lr) * SB + wn * 64 + nt * 8 + lg;
                unsigned b0 = bp[0];
                unsigned b1 = bp[4 * SB];
                MMA_F16(acc[0][nt], a[0], b0, b1);
                MMA_F16(acc[1][nt], a[1], b0, b1);
            }
        }
        if (kt + 1 < KT) {
            unsigned* Ad = As + (cur ^ 1) * ABUF;
            unsigned* Bd = Bs + (cur ^ 1) * BBUF;
            #pragma unroll
            for (int j = 0; j < 4; j++) {
                int f = tid + j * 256;
                int r = f >> 3, kc = f & 7;
                *(uint2*)(Ad + r * SA + kc * 2) = rah[j];
            }
            #pragma unroll
            for (int j = 0; j < 2; j++) {
                int f = tid + j * 256;
                int ng = f & 31, k2 = f >> 5;
                uint4 u;
                u.x = fh2(rb0[j].x, rb1[j].x);
                u.y = fh2(rb0[j].y, rb1[j].y);
                u.z = fh2(rb0[j].z, rb1[j].z);
                u.w = fh2(rb0[j].w, rb1[j].w);
                *(uint4*)(Bd + k2 * SB + ng * 4) = u;
            }
        }
        __syncthreads();
    }

    const float sc = 0.08838834764831845f;  // D^-0.5
    #pragma unroll
    for (int mt = 0; mt < 2; mt++) {
        #pragma unroll
        for (int nt = 0; nt < 8; nt++) {
            int r = row0 + wm * 32 + mt * 16 + lg;
            int c = col0 + wn * 64 + nt * 8 + lr * 2;
            float b0 = bias[c], b1 = bias[c + 1];
            float v0 = acc[mt][nt][0] + b0;
            float v1 = acc[mt][nt][1] + b1;
            float v2 = acc[mt][nt][2] + b0;
            float v3 = acc[mt][nt][3] + b1;
            if (EPI == 0) {
                if (blockIdx.x == 0) {  // q columns
                    v0 *= sc; v1 *= sc; v2 *= sc; v3 *= sc;
                }
                __half* C = (__half*)Cv;
                if (r < n)
                    *(__half2*)(C + (size_t)r * M + c) = __floats2half2_rn(v0, v1);
                if (r + 8 < n)
                    *(__half2*)(C + (size_t)(r + 8) * M + c) = __floats2half2_rn(v2, v3);
            } else {
                float* C = (float*)Cv;
                if (r < n) {
                    float2 rr = *(const float2*)(res + (size_t)r * M + c);
                    *(float2*)(C + (size_t)r * M + c) =
                        make_float2(v0 + rr.x, v1 + rr.y);
                }
                if (r + 8 < n) {
                    float2 rr = *(const float2*)(res + (size_t)(r + 8) * M + c);
                    *(float2*)(C + (size_t)(r + 8) * M + c) =
                        make_float2(v2 + rr.x, v3 + rr.y);
                }
            }
        }
    }
}

// ---------------- fused MLP (fp16 in): out = res + gelu(Y@W1+b1)@W2 + b2 -----
#define SY 68                 // u32 stride for 128-half rows
#define YBUF (128 * SY)
#define FM_SMEM ((2 * YBUF + 2 * BBUF) * 4)  // 87040 B

__global__ __launch_bounds__(256)
void fmlp_kernel(const __half* __restrict__ Y,
                 const float* __restrict__ W1,
                 const float* __restrict__ b1,
                 const float* __restrict__ W2,
                 const float* __restrict__ b2,
                 const float* __restrict__ res,
                 float* __restrict__ C, int n) {
    extern __shared__ unsigned sm[];
    unsigned* Ys = sm;                 // 128 x SY
    unsigned* Hs = sm + YBUF;          // 128 x SY
    unsigned* Bs = sm + 2 * YBUF;      // 2 x BBUF

    const int tid  = threadIdx.x;
    const int lane = tid & 31, warp = tid >> 5;
    const int lg = lane >> 2, lr = lane & 3;
    const int wm = warp & 3,  wn = warp >> 2;
    const int row0 = blockIdx.x * 128;

    // stage Y tile (128 x 128 halves) zero-conversion
    #pragma unroll
    for (int j = 0; j < 16; j++) {
        int f = tid + j * 256;
        int r = f >> 5, c4 = f & 31;
        uint2 v = make_uint2(0u, 0u);
        if (row0 + r < n)
            v = *(const uint2*)(Y + (size_t)(row0 + r) * DDIM + c4 * 4);
        *(uint2*)(Ys + r * SY + c4 * 2) = v;
    }

    float acc2[2][8][4];
    #pragma unroll
    for (int mt = 0; mt < 2; mt++)
        #pragma unroll
        for (int nt = 0; nt < 8; nt++)
            #pragma unroll
            for (int i = 0; i < 4; i++) acc2[mt][nt][i] = 0.f;

    float4 rb0[2], rb1[2];
    __syncthreads();

    for (int cch = 0; cch < 4; cch++) {
        // ---- phase 1: H = Y @ W1[:, cch*128 .. +128] ----
        float acc[2][8][4];
        #pragma unroll
        for (int mt = 0; mt < 2; mt++)
            #pragma unroll
            for (int nt = 0; nt < 8; nt++)
                #pragma unroll
                for (int i = 0; i < 4; i++) acc[mt][nt][i] = 0.f;

        #pragma unroll
        for (int j = 0; j < 2; j++) {
            int f = tid + j * 256;
            int ng = f & 31, k2 = f >> 5;
            float4 w0 = *(const float4*)(W1 + (size_t)(k2 * 2) * 512 + cch * 128 + ng * 4);
            float4 w1 = *(const float4*)(W1 + (size_t)(k2 * 2 + 1) * 512 + cch * 128 + ng * 4);
            uint4 u;
            u.x = fh2(w0.x, w1.x); u.y = fh2(w0.y, w1.y);
            u.z = fh2(w0.z, w1.z); u.w = fh2(w0.w, w1.w);
            *(uint4*)(Bs + k2 * SB + ng * 4) = u;
        }
        __syncthreads();

        #pragma unroll
        for (int kt = 0; kt < 4; kt++) {
            const int cur = kt & 1;
            if (kt < 3) {
                #pragma unroll
                for (int j = 0; j < 2; j++) {
                    int f = tid + j * 256;
                    int ng = f & 31, k2 = f >> 5;
                    int kr = (kt + 1) * 32 + k2 * 2;
                    rb0[j] = *(const float4*)(W1 + (size_t)kr * 512 + cch * 128 + ng * 4);
                    rb1[j] = *(const float4*)(W1 + (size_t)(kr + 1) * 512 + cch * 128 + ng * 4);
                }
            }
            const unsigned* Bb = Bs + cur * BBUF;
            #pragma unroll
            for (int ks = 0; ks < 2; ks++) {
                unsigned a[2][4];
                #pragma unroll
                for (int mt = 0; mt < 2; mt++) {
                    const unsigned* ap = Ys + (wm * 32 + mt * 16 + lg) * SY + (kt * 2 + ks) * 8 + lr;
                    a[mt][0] = ap[0];
                    a[mt][1] = ap[8 * SY];
                    a[mt][2] = ap[4];
                    a[mt][3] = ap[8 * SY + 4];
                }
                #pragma unroll
                for (int nt = 0; nt < 8; nt++) {
                    const unsigned* bp = Bb + (ks * 8 + lr) * SB + wn * 64 + nt * 8 + lg;
                    unsigned b0 = bp[0];
                    unsigned b1v = bp[4 * SB];
                    MMA_F16(acc[0][nt], a[0], b0, b1v);
                    MMA_F16(acc[1][nt], a[1], b0, b1v);
                }
            }
            if (kt < 3) {
                unsigned* Bd = Bs + (cur ^ 1) * BBUF;
                #pragma unroll
                for (int j = 0; j < 2; j++) {
                    int f = tid + j * 256;
                    int ng = f & 31, k2 = f >> 5;
                    uint4 u;
                    u.x = fh2(rb0[j].x, rb1[j].x); u.y = fh2(rb0[j].y, rb1[j].y);
                    u.z = fh2(rb0[j].z, rb1[j].z); u.w = fh2(rb0[j].w, rb1[j].w);
                    *(uint4*)(Bd + k2 * SB + ng * 4) = u;
                }
            }
            __syncthreads();
        }

        // gelu + b1 -> Hs (fp16)
        #pragma unroll
        for (int mt = 0; mt < 2; mt++) {
            #pragma unroll
            for (int nt = 0; nt < 8; nt++) {
                int rloc = wm * 32 + mt * 16 + lg;
                int cu = wn * 32 + nt * 4 + lr;   // u32 column index
                float bb0 = b1[cch * 128 + cu * 2];
                float bb1 = b1[cch * 128 + cu * 2 + 1];
                Hs[rloc * SY + cu] =
                    fh2(gelu_f(acc[mt][nt][0] + bb0), gelu_f(acc[mt][nt][1] + bb1));
                Hs[(rloc + 8) * SY + cu] =
                    fh2(gelu_f(acc[mt][nt][2] + bb0), gelu_f(acc[mt][nt][3] + bb1));
            }
        }
        __syncthreads();

        // ---- phase 2: acc2 += H @ W2[cch*128 .. +128, :] ----
        #pragma unroll
        for (int j = 0; j < 2; j++) {
            int f = tid + j * 256;
            int ng = f & 31, k2 = f >> 5;
            float4 w0 = *(const float4*)(W2 + (size_t)(cch * 128 + k2 * 2) * DDIM + ng * 4);
            float4 w1 = *(const float4*)(W2 + (size_t)(cch * 128 + k2 * 2 + 1) * DDIM + ng * 4);
            uint4 u;
            u.x = fh2(w0.x, w1.x); u.y = fh2(w0.y, w1.y);
            u.z = fh2(w0.z, w1.z); u.w = fh2(w0.w, w1.w);
            *(uint4*)(Bs + k2 * SB + ng * 4) = u;
        }
        __syncthreads();

        #pragma unroll
        for (int kt = 0; kt < 4; kt++) {
            const int cur = kt & 1;
            if (kt < 3) {
                #pragma unroll
                for (int j = 0; j < 2; j++) {
                    int f = tid + j * 256;
                    int ng = f & 31, k2 = f >> 5;
                    int kr = cch * 128 + (kt + 1) * 32 + k2 * 2;
                    rb0[j] = *(const float4*)(W2 + (size_t)kr * DDIM + ng * 4);
                    rb1[j] = *(const float4*)(W2 + (size_t)(kr + 1) * DDIM + ng * 4);
                }
            }
            const unsigned* Bb = Bs + cur * BBUF;
            #pragma unroll
            for (int ks = 0; ks < 2; ks++) {
                unsigned a[2][4];
                #pragma unroll
                for (int mt = 0; mt < 2; mt++) {
                    const unsigned* ap = Hs + (wm * 32 + mt * 16 + lg) * SY + (kt * 2 + ks) * 8 + lr;
                    a[mt][0] = ap[0];
                    a[mt][1] = ap[8 * SY];
                    a[mt][2] = ap[4];
                    a[mt][3] = ap[8 * SY + 4];
                }
                #pragma unroll
                for (int nt = 0; nt < 8; nt++) {
                    const unsigned* bp = Bb + (ks * 8 + lr) * SB + wn * 64 + nt * 8 + lg;
                    unsigned b0 = bp[0];
                    unsigned b1v = bp[4 * SB];
                    MMA_F16(acc2[0][nt], a[0], b0, b1v);
                    MMA_F16(acc2[1][nt], a[1], b0, b1v);
                }
            }
            if (kt < 3) {
                unsigned* Bd = Bs + (cur ^ 1) * BBUF;
                #pragma unroll
                for (int j = 0; j < 2; j++) {
                    int f = tid + j * 256;
                    int ng = f & 31, k2 = f >> 5;
                    uint4 u;
                    u.x = fh2(rb0[j].x, rb1[j].x); u.y = fh2(rb0[j].y, rb1[j].y);
                    u.z = fh2(rb0[j].z, rb1[j].z); u.w = fh2(rb0[j].w, rb1[j].w);
                    *(uint4*)(Bd + k2 * SB + ng * 4) = u;
                }
            }
            __syncthreads();
        }
    }

    // epilogue: + b2 + res
    #pragma unroll
    for (int mt = 0; mt < 2; mt++) {
        #pragma unroll
        for (int nt = 0; nt < 8; nt++) {
            int r = row0 + wm * 32 + mt * 16 + lg;
            int c = wn * 64 + nt * 8 + lr * 2;
            float bb0 = b2[c], bb1 = b2[c + 1];
            if (r < n) {
                float2 rr = *(const float2*)(res + (size_t)r * DDIM + c);
                *(float2*)(C + (size_t)r * DDIM + c) =
                    make_float2(acc2[mt][nt][0] + bb0 + rr.x,
                                acc2[mt][nt][1] + bb1 + rr.y);
            }
            if (r + 8 < n) {
                float2 rr = *(const float2*)(res + (size_t)(r + 8) * DDIM + c);
                *(float2*)(C + (size_t)(r + 8) * DDIM + c) =
                    make_float2(acc2[mt][nt][2] + bb0 + rr.x,
                                acc2[mt][nt][3] + bb1 + rr.y);
            }
        }
    }
}

// ---------------- launch ----------------
extern "C" void kernel_launch(void* const* d_in, const int* in_sizes, int n_in,
                              void* d_out, int out_size) {
    const float* node_feature = (const float*)d_in[0];
    const float* dist_attn    = (const float*)d_in[1];
    const float* path_attn    = (const float*)d_in[2];
    const int*   src          = (const int*)d_in[3];
    const int*   dst          = (const int*)d_in[4];
    const float* ln1_g        = (const float*)d_in[5];
    const float* ln1_b        = (const float*)d_in[6];
    const float* qkv_w        = (const float*)d_in[7];
    const float* qkv_b        = (const float*)d_in[8];
    const float* in_proj_w    = (const float*)d_in[9];
    const float* in_proj_b    = (const float*)d_in[10];
    const float* res_ln_g     = (const float*)d_in[11];
    const float* res_ln_b     = (const float*)d_in[12];
    const float* mlp_w1       = (const float*)d_in[13];
    const float* mlp_b1       = (const float*)d_in[14];
    const float* mlp_w2       = (const float*)d_in[15];
    const float* mlp_b2       = (const float*)d_in[16];
    float* out = (float*)d_out;

    cudaFuncSetAttribute(gemm_tc<0>, cudaFuncAttributeMaxDynamicSharedMemorySize, GM_SMEM);
    cudaFuncSetAttribute(gemm_tc<1>, cudaFuncAttributeMaxDynamicSharedMemorySize, GM_SMEM);
    cudaFuncSetAttribute(fmlp_kernel, cudaFuncAttributeMaxDynamicSharedMemorySize, FM_SMEM);

    void* p;
    cudaGetSymbolAddress(&p, g_h);    float*  ph   = (float*)p;
    cudaGetSymbolAddress(&p, g_hh);   __half* phh  = (__half*)p;
    cudaGetSymbolAddress(&p, g_qkv);  __half* pqkv = (__half*)p;
    cudaGetSymbolAddress(&p, g_agg);  __half* pagg = (__half*)p;
    cudaGetSymbolAddress(&p, g_x);    float*  px   = (float*)p;
    cudaGetSymbolAddress(&p, g_yh);   __half* pyh  = (__half*)p;

    const int RB = (NN + 127) / 128;           // 391 row blocks
    const int LN_BLOCKS = (NN + 7) / 8;
    const int E_BLOCKS  = (EE + 255) / 256;
    const int ATTN_BLOCKS = (NN * 32 + 255) / 256;

    // CSR build (+ precompute of src & dist+path in CSR order)
    zero_ln_kernel<<<NBLK + LN_BLOCKS, 256>>>(node_feature, ln1_g, ln1_b, ph, phh);
    hist_kernel<<<E_BLOCKS, 256>>>(dst);
    scanA_kernel<<<NB, 256>>>();
    scanBC_kernel<<<NB, 256>>>();
    scatter_kernel<<<E_BLOCKS, 256>>>(src, dst, dist_attn, path_attn);

    // main pipeline
    gemm_tc<0><<<dim3(3, RB), 256, GM_SMEM>>>(phh, qkv_w, qkv_b, nullptr, pqkv, NN, 384, 128);
    attn_kernel<<<ATTN_BLOCKS, 256>>>();
    gemm_tc<1><<<dim3(1, RB), 256, GM_SMEM>>>(pagg, in_proj_w, in_proj_b, ph, px, NN, 128, 128);
    ln_kernel<<<LN_BLOCKS, 256>>>(px, res_ln_g, res_ln_b, pyh, NN);
    fmlp_kernel<<<RB, 256, FM_SMEM>>>(pyh, mlp_w1, mlp_b1, mlp_w2, mlp_b2, px, out, NN);
}